// round 2
// baseline (speedup 1.0000x reference)
#include <cuda_runtime.h>

#define NR 1024
#define NC 1024
#define EPS 1e-5f

// ---- scratch (static __device__ arrays; no allocation) ----
__device__ float g_I[20 * 20 * 1024];        // integral image, layout [y][x][c]
__device__ float g_pooled[NR * NC * 25];     // [roi][c][5x5]
__device__ float g_wT1[9216 * 256];          // [k = ic*9+tap][oc]
__device__ float g_wT2[2304 * 256];          // [k = ic*9+tap][oc]
__device__ float g_h1[NR * 256 * 9];         // conv1 output [roi][oc][3x3]

// ---------------------------------------------------------------------------
// Weight transposes: w[oc][k] -> wT[k][oc] so conv threads load float4 over oc
// ---------------------------------------------------------------------------
__global__ void k_transpose_w1(const float* __restrict__ w1) {
    int idx = blockIdx.x * 256 + threadIdx.x;
    if (idx >= 256 * 9216) return;
    int oc = idx / 9216;
    int k  = idx - oc * 9216;
    g_wT1[k * 256 + oc] = w1[idx];
}

__global__ void k_transpose_w2(const float* __restrict__ w2) {
    int idx = blockIdx.x * 256 + threadIdx.x;
    if (idx >= 256 * 2304) return;
    int oc = idx / 2304;
    int k  = idx - oc * 2304;
    g_wT2[k * 256 + oc] = w2[idx];
}

// ---------------------------------------------------------------------------
// Per-channel 2D integral image. One thread per channel; prev row in registers.
// I[(y)(x)][c] with zero row/col at y=0 / x=0. I[y+1][x+1] = sum f[0..y][0..x].
// ---------------------------------------------------------------------------
__global__ void k_integral(const float* __restrict__ f) {
    int c = blockIdx.x * 256 + threadIdx.x;
    if (c >= 1024) return;
    float prev[19];
    g_I[c] = 0.f;  // (0,0)
#pragma unroll
    for (int x = 0; x < 19; x++) {
        g_I[(x + 1) * 1024 + c] = 0.f;  // row 0
        prev[x] = 0.f;
    }
    for (int y = 0; y < 19; y++) {
        g_I[((y + 1) * 20) * 1024 + c] = 0.f;  // col 0
        float rs = 0.f;
#pragma unroll
        for (int x = 0; x < 19; x++) {
            rs += f[c * 361 + y * 19 + x];
            float cur = rs + prev[x];
            g_I[((y + 1) * 20 + x + 1) * 1024 + c] = cur;
            prev[x] = cur;
        }
    }
}

// ---------------------------------------------------------------------------
// RoI pooling via integral-image rectangle means.
// Uniform pool weight 1/(end-start) => pooled cell = mean over bin rectangle.
// One block per roi; threads stride over channels (coalesced: c is innermost
// in g_I layout).
// ---------------------------------------------------------------------------
__global__ void k_pool(const float* __restrict__ rois) {
    int r   = blockIdx.x;
    int tid = threadIdx.x;

    const float S = 300.0f / 16.0f;  // 18.75 exactly representable
    float fxm = rois[r * 5 + 1] * S;
    float fym = rois[r * 5 + 2] * S;
    float fxM = rois[r * 5 + 3] * S;
    float fyM = rois[r * 5 + 4] * S;
    int x_min = min(max((int)fxm, 1), 18);
    int y_min = min(max((int)fym, 1), 18);
    int x_max = min(max((int)fxM, 1), 18);
    int y_max = min(max((int)fyM, 1), 18);
    if (x_max == x_min) x_min -= 1;
    if (y_max == y_min) y_min -= 1;
    int nx = x_max - x_min + 1;
    int ny = y_max - y_min + 1;

    int ys[5], ye[5], xs[5], xe[5];
    float wy[5], wx[5];
#pragma unroll
    for (int i = 0; i < 5; i++) {
        ys[i] = y_min + (i * ny) / 5;
        ye[i] = y_min + ((i + 1) * ny + 4) / 5;
        wy[i] = 1.0f / (float)(ye[i] - ys[i]);
        xs[i] = x_min + (i * nx) / 5;
        xe[i] = x_min + ((i + 1) * nx + 4) / 5;
        wx[i] = 1.0f / (float)(xe[i] - xs[i]);
    }

    for (int c = tid; c < 1024; c += 256) {
        float* op = g_pooled + r * 25600 + c * 25;
#pragma unroll
        for (int i = 0; i < 5; i++) {
#pragma unroll
            for (int j = 0; j < 5; j++) {
                float a  = g_I[(ye[i] * 20 + xe[j]) * 1024 + c];
                float b_ = g_I[(ys[i] * 20 + xe[j]) * 1024 + c];
                float d_ = g_I[(ye[i] * 20 + xs[j]) * 1024 + c];
                float e_ = g_I[(ys[i] * 20 + xs[j]) * 1024 + c];
                op[i * 5 + j] = (a - b_ - d_ + e_) * (wy[i] * wx[j]);
            }
        }
    }
}

// ---------------------------------------------------------------------------
// conv1 (1024->256, 3x3, stride 2, pad 1, in 5x5 -> out 3x3) + BN + ReLU.
// Block = 128 threads = 2 rois x 64 oc-quads. Thread: 4 oc x 9 positions.
// Inputs held in 25 registers per ic; weights one coalesced float4/tap.
// Zero-padding taps pruned at compile time: 49/81 valid combos -> 196 FMA/ic.
// ---------------------------------------------------------------------------
__global__ void __launch_bounds__(128) k_conv1(
    const float* __restrict__ b1, const float* __restrict__ g1,
    const float* __restrict__ be1, const float* __restrict__ m1,
    const float* __restrict__ v1) {
    int tid = threadIdx.x;
    int roi = blockIdx.x * 2 + (tid >> 6);
    int oc0 = (tid & 63) * 4;
    const float* inp = g_pooled + roi * 25600;
    const float* wp  = g_wT1 + oc0;

    float acc[4][9];
#pragma unroll
    for (int q = 0; q < 4; q++)
#pragma unroll
        for (int p = 0; p < 9; p++) acc[q][p] = 0.f;

#pragma unroll 1
    for (int ic = 0; ic < 1024; ic++) {
        float in[25];
#pragma unroll
        for (int p = 0; p < 25; p++) in[p] = __ldg(inp + ic * 25 + p);
#pragma unroll
        for (int t = 0; t < 9; t++) {
            float4 w = __ldg((const float4*)(wp + (ic * 9 + t) * 256));
            int ky = t / 3, kx = t % 3;
#pragma unroll
            for (int i = 0; i < 3; i++) {
                int y = 2 * i - 1 + ky;
                if (y < 0 || y > 4) continue;
#pragma unroll
                for (int j = 0; j < 3; j++) {
                    int x = 2 * j - 1 + kx;
                    if (x < 0 || x > 4) continue;
                    float v = in[y * 5 + x];
                    int p = i * 3 + j;
                    acc[0][p] = fmaf(w.x, v, acc[0][p]);
                    acc[1][p] = fmaf(w.y, v, acc[1][p]);
                    acc[2][p] = fmaf(w.z, v, acc[2][p]);
                    acc[3][p] = fmaf(w.w, v, acc[3][p]);
                }
            }
        }
    }

#pragma unroll
    for (int q = 0; q < 4; q++) {
        int oc = oc0 + q;
        float sc = __ldg(g1 + oc) * rsqrtf(__ldg(v1 + oc) + EPS);
        float sh = __ldg(be1 + oc) - __ldg(m1 + oc) * sc;
        float bb = __ldg(b1 + oc);
#pragma unroll
        for (int p = 0; p < 9; p++) {
            float yv = (acc[q][p] + bb) * sc + sh;
            g_h1[roi * 2304 + oc * 9 + p] = fmaxf(yv, 0.f);
        }
    }
}

// ---------------------------------------------------------------------------
// conv2 (256->256, 3x3, stride 2, pad 1, in 3x3 -> out 2x2) + BN + ReLU.
// Same structure. 16/36 valid (tap,pos) combos -> 64 FMA per ic per thread.
// Output written directly to d_out: shape (1, R, 256, 2, 2), img_idx == 0.
// ---------------------------------------------------------------------------
__global__ void __launch_bounds__(128) k_conv2(
    const float* __restrict__ b2, const float* __restrict__ g2,
    const float* __restrict__ be2, const float* __restrict__ m2,
    const float* __restrict__ v2, float* __restrict__ out) {
    int tid = threadIdx.x;
    int roi = blockIdx.x * 2 + (tid >> 6);
    int oc0 = (tid & 63) * 4;
    const float* inp = g_h1 + roi * 2304;
    const float* wp  = g_wT2 + oc0;

    float acc[4][4];
#pragma unroll
    for (int q = 0; q < 4; q++)
#pragma unroll
        for (int p = 0; p < 4; p++) acc[q][p] = 0.f;

#pragma unroll 1
    for (int ic = 0; ic < 256; ic++) {
        float in[9];
#pragma unroll
        for (int p = 0; p < 9; p++) in[p] = __ldg(inp + ic * 9 + p);
#pragma unroll
        for (int t = 0; t < 9; t++) {
            float4 w = __ldg((const float4*)(wp + (ic * 9 + t) * 256));
            int ky = t / 3, kx = t % 3;
#pragma unroll
            for (int i = 0; i < 2; i++) {
                int y = 2 * i - 1 + ky;
                if (y < 0 || y > 2) continue;
#pragma unroll
                for (int j = 0; j < 2; j++) {
                    int x = 2 * j - 1 + kx;
                    if (x < 0 || x > 2) continue;
                    float v = in[y * 3 + x];
                    int p = i * 2 + j;
                    acc[0][p] = fmaf(w.x, v, acc[0][p]);
                    acc[1][p] = fmaf(w.y, v, acc[1][p]);
                    acc[2][p] = fmaf(w.z, v, acc[2][p]);
                    acc[3][p] = fmaf(w.w, v, acc[3][p]);
                }
            }
        }
    }

#pragma unroll
    for (int q = 0; q < 4; q++) {
        int oc = oc0 + q;
        float sc = __ldg(g2 + oc) * rsqrtf(__ldg(v2 + oc) + EPS);
        float sh = __ldg(be2 + oc) - __ldg(m2 + oc) * sc;
        float bb = __ldg(b2 + oc);
#pragma unroll
        for (int p = 0; p < 4; p++) {
            float yv = (acc[q][p] + bb) * sc + sh;
            out[roi * 1024 + oc * 4 + p] = fmaxf(yv, 0.f);
        }
    }
}

// ---------------------------------------------------------------------------
extern "C" void kernel_launch(void* const* d_in, const int* in_sizes, int n_in,
                              void* d_out, int out_size) {
    const float* rois     = (const float*)d_in[0];
    const float* features = (const float*)d_in[1];
    const float* w1       = (const float*)d_in[2];
    const float* b1       = (const float*)d_in[3];
    const float* g1       = (const float*)d_in[4];
    const float* be1      = (const float*)d_in[5];
    const float* m1       = (const float*)d_in[6];
    const float* v1       = (const float*)d_in[7];
    const float* w2       = (const float*)d_in[8];
    const float* b2       = (const float*)d_in[9];
    const float* g2       = (const float*)d_in[10];
    const float* be2      = (const float*)d_in[11];
    const float* m2       = (const float*)d_in[12];
    const float* v2       = (const float*)d_in[13];
    float* out = (float*)d_out;

    k_transpose_w1<<<(256 * 9216 + 255) / 256, 256>>>(w1);
    k_transpose_w2<<<(256 * 2304 + 255) / 256, 256>>>(w2);
    k_integral<<<4, 256>>>(features);
    k_pool<<<1024, 256>>>(rois);
    k_conv1<<<512, 128>>>(b1, g1, be1, m1, v1);
    k_conv2<<<512, 128>>>(b2, g2, be2, m2, v2, out);
}

// round 4
// speedup vs baseline: 2.2789x; 2.2789x over previous
#include <cuda_runtime.h>

#define EPS 1e-5f
typedef unsigned long long u64;

// ---- scratch (static __device__; no allocation) ----
__device__ float g_I[20 * 20 * 1024];        // integral image [y][x][c]
__device__ float g_pooled[1024 * 25 * 1024]; // [roi][p][c]
__device__ float g_wT1[9216 * 256];          // [k=ic*9+t][oc]
__device__ float g_wT2[2304 * 256];
__device__ float g_h1[1024 * 9 * 256];       // [roi][p][oc]

// ---- packed f32x2 helpers (sm_103a FFMA2 path) ----
__device__ __forceinline__ void fma2(u64& a, u64 w, u64 v) {
    asm("fma.rn.f32x2 %0, %1, %2, %0;" : "+l"(a) : "l"(w), "l"(v));
}
__device__ __forceinline__ u64 pack2(float v) {
    u64 r; asm("mov.b64 %0, {%1, %1};" : "=l"(r) : "f"(v)); return r;
}
__device__ __forceinline__ float2 unpack2(u64 a) {
    float2 f; asm("mov.b64 {%0, %1}, %2;" : "=f"(f.x), "=f"(f.y) : "l"(a)); return f;
}

// ---------------------------------------------------------------------------
// Coalesced tiled transpose: in[256][K] -> out[K][256]
// ---------------------------------------------------------------------------
__global__ void k_transpose(const float* __restrict__ in, float* __restrict__ out, int K) {
    __shared__ float tile[32][33];
    int k0 = blockIdx.x * 32, o0 = blockIdx.y * 32;
#pragma unroll
    for (int r = threadIdx.y; r < 32; r += 8)
        tile[r][threadIdx.x] = in[(o0 + r) * K + k0 + threadIdx.x];
    __syncthreads();
#pragma unroll
    for (int r = threadIdx.y; r < 32; r += 8)
        out[(k0 + r) * 256 + o0 + threadIdx.x] = tile[threadIdx.x][r];
}

// ---------------------------------------------------------------------------
// Per-channel 2D integral image (19x19 -> 20x20 with zero borders), [y][x][c]
// ---------------------------------------------------------------------------
__global__ void k_integral(const float* __restrict__ f) {
    int c = blockIdx.x * 256 + threadIdx.x;
    if (c >= 1024) return;
    float prev[19];
    g_I[c] = 0.f;
#pragma unroll
    for (int x = 0; x < 19; x++) {
        g_I[(x + 1) * 1024 + c] = 0.f;
        prev[x] = 0.f;
    }
    for (int y = 0; y < 19; y++) {
        g_I[((y + 1) * 20) * 1024 + c] = 0.f;
        float rs = 0.f;
#pragma unroll
        for (int x = 0; x < 19; x++) {
            rs += f[c * 361 + y * 19 + x];
            float cur = rs + prev[x];
            g_I[((y + 1) * 20 + x + 1) * 1024 + c] = cur;
            prev[x] = cur;
        }
    }
}

// ---------------------------------------------------------------------------
// RoI pool via integral rectangle means. Offsets/weights precomputed in smem
// (low regs -> high occupancy). Output [roi][p][c]: coalesced writes.
// ---------------------------------------------------------------------------
__global__ void __launch_bounds__(256) k_pool(const float* __restrict__ rois) {
    __shared__ int sA[25], sB[25], sC[25], sD[25];
    __shared__ float sW[25];
    int r = blockIdx.x, tid = threadIdx.x;
    if (tid < 25) {
        const float S = 18.75f;
        float fxm = rois[r * 5 + 1] * S, fym = rois[r * 5 + 2] * S;
        float fxM = rois[r * 5 + 3] * S, fyM = rois[r * 5 + 4] * S;
        int x_min = min(max((int)fxm, 1), 18), y_min = min(max((int)fym, 1), 18);
        int x_max = min(max((int)fxM, 1), 18), y_max = min(max((int)fyM, 1), 18);
        if (x_max == x_min) x_min--;
        if (y_max == y_min) y_min--;
        int nx = x_max - x_min + 1, ny = y_max - y_min + 1;
        int i = tid / 5, j = tid % 5;
        int ys = y_min + (i * ny) / 5, ye = y_min + ((i + 1) * ny + 4) / 5;
        int xs = x_min + (j * nx) / 5, xe = x_min + ((j + 1) * nx + 4) / 5;
        sA[tid] = (ye * 20 + xe) * 1024;
        sB[tid] = (ys * 20 + xe) * 1024;
        sC[tid] = (ye * 20 + xs) * 1024;
        sD[tid] = (ys * 20 + xs) * 1024;
        sW[tid] = (1.0f / (float)(ye - ys)) * (1.0f / (float)(xe - xs));
    }
    __syncthreads();
    float* op = g_pooled + r * 25 * 1024;
    for (int c = tid; c < 1024; c += 256) {
#pragma unroll 5
        for (int p = 0; p < 25; p++) {
            float v = g_I[sA[p] + c] - g_I[sB[p] + c] - g_I[sC[p] + c] + g_I[sD[p] + c];
            op[p * 1024 + c] = v * sW[p];
        }
    }
}

// ---------------------------------------------------------------------------
// conv1 (1024->256, 3x3, s2, p1, 5x5 -> 3x3) + BN + ReLU, packed f32x2.
// Block = 256 thr = 4 rois x 64 oc-quads. Inputs staged in smem per 8-ic tile
// (LDS broadcast), weights float4 LDG shared across the 4 roi groups via L1.
// ---------------------------------------------------------------------------
#define ICT 8
__global__ void __launch_bounds__(256, 2) k_conv1(
    const float* __restrict__ b1, const float* __restrict__ g1,
    const float* __restrict__ be1, const float* __restrict__ m1,
    const float* __restrict__ v1) {
    __shared__ float s_in[4 * 25 * ICT];  // [roi][p][icl]
    int tid = threadIdx.x;
    int roiL = tid >> 6;
    int oc0 = (tid & 63) * 4;
    int roi0 = blockIdx.x * 4;

    u64 acc[9][2];
#pragma unroll
    for (int p = 0; p < 9; p++) { acc[p][0] = 0ull; acc[p][1] = 0ull; }

    // staging roles: 200 threads load 4 rois x 25 cells x 8 ics (2 float4 each)
    int sroi = tid / 50, srem = tid % 50, sp = srem / 2, shalf = srem % 2;
    const float4* sg = (const float4*)(g_pooled + ((roi0 + sroi) * 25 + sp) * 1024 + shalf * 4);
    float4* ss = (float4*)(s_in + (sroi * 25 + sp) * ICT + shalf * 4);

    const float* wbase = g_wT1 + oc0;

    for (int ic0 = 0; ic0 < 1024; ic0 += ICT) {
        __syncthreads();
        if (tid < 200) *ss = sg[ic0 / 4];
        __syncthreads();
#pragma unroll
        for (int icl = 0; icl < ICT; icl++) {
            float in[25];
#pragma unroll
            for (int p = 0; p < 25; p++) in[p] = s_in[(roiL * 25 + p) * ICT + icl];
            const float* wp = wbase + (ic0 + icl) * 9 * 256;
#pragma unroll
            for (int t = 0; t < 9; t++) {
                ulonglong2 w = *(const ulonglong2*)(wp + t * 256);
                int ky = t / 3, kx = t % 3;
#pragma unroll
                for (int i = 0; i < 3; i++) {
                    int y = 2 * i - 1 + ky;
                    if (y < 0 || y > 4) continue;
#pragma unroll
                    for (int j = 0; j < 3; j++) {
                        int x = 2 * j - 1 + kx;
                        if (x < 0 || x > 4) continue;
                        u64 vv = pack2(in[y * 5 + x]);
                        int p = i * 3 + j;
                        fma2(acc[p][0], w.x, vv);
                        fma2(acc[p][1], w.y, vv);
                    }
                }
            }
        }
    }

    int roi = roi0 + roiL;
    float sc[4], sh[4];
#pragma unroll
    for (int q = 0; q < 4; q++) {
        int oc = oc0 + q;
        float s = __ldg(g1 + oc) * rsqrtf(__ldg(v1 + oc) + EPS);
        sc[q] = s;
        sh[q] = __ldg(be1 + oc) - __ldg(m1 + oc) * s + __ldg(b1 + oc) * s;
    }
#pragma unroll
    for (int p = 0; p < 9; p++) {
        float2 a0 = unpack2(acc[p][0]);
        float2 a1 = unpack2(acc[p][1]);
        float4 o;
        o.x = fmaxf(a0.x * sc[0] + sh[0], 0.f);
        o.y = fmaxf(a0.y * sc[1] + sh[1], 0.f);
        o.z = fmaxf(a1.x * sc[2] + sh[2], 0.f);
        o.w = fmaxf(a1.y * sc[3] + sh[3], 0.f);
        *(float4*)(g_h1 + (roi * 9 + p) * 256 + oc0) = o;
    }
}

// ---------------------------------------------------------------------------
// conv2 (256->256, 3x3, s2, p1, 3x3 -> 2x2) + BN + ReLU, packed f32x2.
// Same structure. Writes final output (B=1, img_idx=0): out[roi][oc][2x2].
// ---------------------------------------------------------------------------
__global__ void __launch_bounds__(256, 2) k_conv2(
    const float* __restrict__ b2, const float* __restrict__ g2,
    const float* __restrict__ be2, const float* __restrict__ m2,
    const float* __restrict__ v2, float* __restrict__ out) {
    __shared__ float s_in[4 * 9 * ICT];  // [roi][p][icl]
    int tid = threadIdx.x;
    int roiL = tid >> 6;
    int oc0 = (tid & 63) * 4;
    int roi0 = blockIdx.x * 4;

    u64 acc[4][2];
#pragma unroll
    for (int p = 0; p < 4; p++) { acc[p][0] = 0ull; acc[p][1] = 0ull; }

    int sroi = tid / 18, srem = tid % 18, sp = srem / 2, shalf = srem % 2;
    const float4* sg = (const float4*)(g_h1 + ((roi0 + min(sroi, 3)) * 9 + sp) * 256 + shalf * 4);
    float4* ss = (float4*)(s_in + (min(sroi, 3) * 9 + sp) * ICT + shalf * 4);

    const float* wbase = g_wT2 + oc0;

    for (int ic0 = 0; ic0 < 256; ic0 += ICT) {
        __syncthreads();
        if (tid < 72) *ss = sg[ic0 / 4];
        __syncthreads();
#pragma unroll
        for (int icl = 0; icl < ICT; icl++) {
            float in[9];
#pragma unroll
            for (int p = 0; p < 9; p++) in[p] = s_in[(roiL * 9 + p) * ICT + icl];
            const float* wp = wbase + (ic0 + icl) * 9 * 256;
#pragma unroll
            for (int t = 0; t < 9; t++) {
                ulonglong2 w = *(const ulonglong2*)(wp + t * 256);
                int ky = t / 3, kx = t % 3;
#pragma unroll
                for (int i = 0; i < 2; i++) {
                    int y = 2 * i - 1 + ky;
                    if (y < 0 || y > 2) continue;
#pragma unroll
                    for (int j = 0; j < 2; j++) {
                        int x = 2 * j - 1 + kx;
                        if (x < 0 || x > 2) continue;
                        u64 vv = pack2(in[y * 3 + x]);
                        int p = i * 2 + j;
                        fma2(acc[p][0], w.x, vv);
                        fma2(acc[p][1], w.y, vv);
                    }
                }
            }
        }
    }

    int roi = roi0 + roiL;
    float sc[4], sh[4];
#pragma unroll
    for (int q = 0; q < 4; q++) {
        int oc = oc0 + q;
        float s = __ldg(g2 + oc) * rsqrtf(__ldg(v2 + oc) + EPS);
        sc[q] = s;
        sh[q] = __ldg(be2 + oc) - __ldg(m2 + oc) * s + __ldg(b2 + oc) * s;
    }
    float a[4][4];
#pragma unroll
    for (int p = 0; p < 4; p++) {
        float2 x0 = unpack2(acc[p][0]);
        float2 x1 = unpack2(acc[p][1]);
        a[p][0] = x0.x; a[p][1] = x0.y; a[p][2] = x1.x; a[p][3] = x1.y;
    }
#pragma unroll
    for (int q = 0; q < 4; q++) {
        float4 o;
        o.x = fmaxf(a[0][q] * sc[q] + sh[q], 0.f);
        o.y = fmaxf(a[1][q] * sc[q] + sh[q], 0.f);
        o.z = fmaxf(a[2][q] * sc[q] + sh[q], 0.f);
        o.w = fmaxf(a[3][q] * sc[q] + sh[q], 0.f);
        *(float4*)(out + roi * 1024 + (oc0 + q) * 4) = o;
    }
}

// ---------------------------------------------------------------------------
extern "C" void kernel_launch(void* const* d_in, const int* in_sizes, int n_in,
                              void* d_out, int out_size) {
    const float* rois     = (const float*)d_in[0];
    const float* features = (const float*)d_in[1];
    const float* w1       = (const float*)d_in[2];
    const float* b1       = (const float*)d_in[3];
    const float* g1       = (const float*)d_in[4];
    const float* be1      = (const float*)d_in[5];
    const float* m1       = (const float*)d_in[6];
    const float* v1       = (const float*)d_in[7];
    const float* w2       = (const float*)d_in[8];
    const float* b2       = (const float*)d_in[9];
    const float* g2       = (const float*)d_in[10];
    const float* be2      = (const float*)d_in[11];
    const float* m2       = (const float*)d_in[12];
    const float* v2       = (const float*)d_in[13];
    float* out = (float*)d_out;

    {
        float* wT1p; cudaGetSymbolAddress((void**)&wT1p, g_wT1);
        float* wT2p; cudaGetSymbolAddress((void**)&wT2p, g_wT2);
        dim3 t(32, 8);
        k_transpose<<<dim3(288, 8), t>>>(w1, wT1p, 9216);
        k_transpose<<<dim3(72, 8), t>>>(w2, wT2p, 2304);
    }
    k_integral<<<4, 256>>>(features);
    k_pool<<<1024, 256>>>(rois);
    k_conv1<<<256, 256>>>(b1, g1, be1, m1, v1);
    k_conv2<<<256, 256>>>(b2, g2, be2, m2, v2, out);
}

// round 12
// speedup vs baseline: 4.2192x; 1.8514x over previous
#include <cuda_runtime.h>
#include <cuda_bf16.h>
#include <cstdint>
#include <cstddef>

typedef unsigned long long u64;
#define EPS 1e-5f

// ---- scratch (static __device__; no allocation) ----
__device__ float g_I[20 * 20 * 1024];            // integral image [y][x][c]
__device__ __nv_bfloat16 g_Ahi[256 * 9216];      // weights hi [oc][k=t*1024+ic]
__device__ __nv_bfloat16 g_Alo[256 * 9216];      // weights lo
__device__ __nv_bfloat16 g_Bhi[9216ull * 9216];  // im2col hi [n=roi*9+p][k]
__device__ __nv_bfloat16 g_Blo[9216ull * 9216];  // im2col lo
__device__ float g_h1[256 * 9216];               // conv1 out TRANSPOSED [oc][n]
__device__ float g_wT2[2304 * 256];              // conv2 weights [k][oc]

// ---- packed f32x2 helpers (conv2) ----
__device__ __forceinline__ void fma2(u64& a, u64 w, u64 v) {
    asm("fma.rn.f32x2 %0, %1, %2, %0;" : "+l"(a) : "l"(w), "l"(v));
}
__device__ __forceinline__ u64 pack2(float v) {
    u64 r;
    asm("mov.b64 %0, {%1, %1};" : "=l"(r) : "f"(v));
    return r;
}
__device__ __forceinline__ float2 unpack2(u64 a) {
    float2 f;
    asm("mov.b64 {%0, %1}, %2;" : "=f"(f.x), "=f"(f.y) : "l"(a));
    return f;
}

// ---- mma.sync / ldmatrix / cp.async helpers (plain sm_103-legal) ----
__device__ __forceinline__ unsigned int smem_u32(const void* p) {
    unsigned int a;
    asm("{ .reg .u64 t; cvta.to.shared.u64 t, %1; cvt.u32.u64 %0, t; }" : "=r"(a) : "l"(p));
    return a;
}
__device__ __forceinline__ void ldsm4(unsigned int* r, unsigned int addr) {
    asm volatile("ldmatrix.sync.aligned.m8n8.x4.shared.b16 {%0,%1,%2,%3}, [%4];"
                 : "=r"(r[0]), "=r"(r[1]), "=r"(r[2]), "=r"(r[3]) : "r"(addr));
}
__device__ __forceinline__ void mma_bf16(float* c, const unsigned int* a,
                                         unsigned int b0, unsigned int b1) {
    asm volatile(
        "mma.sync.aligned.m16n8k16.row.col.f32.bf16.bf16.f32 "
        "{%0,%1,%2,%3}, {%4,%5,%6,%7}, {%8,%9}, {%0,%1,%2,%3};"
        : "+f"(c[0]), "+f"(c[1]), "+f"(c[2]), "+f"(c[3])
        : "r"(a[0]), "r"(a[1]), "r"(a[2]), "r"(a[3]), "r"(b0), "r"(b1));
}
__device__ __forceinline__ void cpa16(unsigned int dst, const void* src) {
    asm volatile("cp.async.cg.shared.global [%0], [%1], 16;" :: "r"(dst), "l"(src));
}

// ---------------------------------------------------------------------------
// conv2 weight transpose: in[256][K] -> out[K][256]
// ---------------------------------------------------------------------------
__global__ void k_transpose(const float* __restrict__ in, float* __restrict__ out, int K) {
    __shared__ float tile[32][33];
    int k0 = blockIdx.x * 32, o0 = blockIdx.y * 32;
    for (int r = threadIdx.y; r < 32; r += 8)
        tile[r][threadIdx.x] = in[(o0 + r) * K + k0 + threadIdx.x];
    __syncthreads();
    for (int r = threadIdx.y; r < 32; r += 8)
        out[(k0 + r) * 256 + o0 + threadIdx.x] = tile[threadIdx.x][r];
}

// ---------------------------------------------------------------------------
// Per-channel 2D integral image (19x19 -> 20x20 zero-bordered), [y][x][c]
// ---------------------------------------------------------------------------
__global__ void k_integral(const float* __restrict__ f) {
    int c = blockIdx.x * 256 + threadIdx.x;
    if (c >= 1024) return;
    float prev[19];
    g_I[c] = 0.f;
    for (int x = 0; x < 19; x++) {
        g_I[(x + 1) * 1024 + c] = 0.f;
        prev[x] = 0.f;
    }
    for (int y = 0; y < 19; y++) {
        g_I[((y + 1) * 20) * 1024 + c] = 0.f;
        float rs = 0.f;
        for (int x = 0; x < 19; x++) {
            rs += f[c * 361 + y * 19 + x];
            float cur = rs + prev[x];
            g_I[((y + 1) * 20 + x + 1) * 1024 + c] = cur;
            prev[x] = cur;
        }
    }
}

// ---------------------------------------------------------------------------
// A build: w1[oc][ic][t] -> Ahi/Alo[oc][k = t*1024+ic], bf16 hi/lo split
// ---------------------------------------------------------------------------
__global__ void k_build_a(const float* __restrict__ w1) {
    int idx = blockIdx.x * 256 + threadIdx.x;
    int m = idx / 9216, k = idx - m * 9216;
    int t = k >> 10, ic = k & 1023;
    float w = w1[m * 9216 + ic * 9 + t];
    __nv_bfloat16 hi = __float2bfloat16(w);
    g_Ahi[idx] = hi;
    g_Alo[idx] = __float2bfloat16(w - __bfloat162float(hi));
}

// ---------------------------------------------------------------------------
// B build (fused RoI pooling + im2col). Row n = roi*9+p; B[n][t*1024+c] =
// rect-mean via integral image, 0 for padding taps. Coalesced 1024-wide runs.
// ---------------------------------------------------------------------------
__global__ void __launch_bounds__(256) k_build_b(const float* __restrict__ rois) {
    __shared__ int sA[9], sB[9], sC[9], sD[9];
    __shared__ float sW[9];
    int bx = blockIdx.x;
    int r = bx / 9, p = bx - r * 9;
    int tid = threadIdx.x;
    if (tid < 9) {
        const float S = 18.75f;
        float fxm = rois[r * 5 + 1] * S, fym = rois[r * 5 + 2] * S;
        float fxM = rois[r * 5 + 3] * S, fyM = rois[r * 5 + 4] * S;
        int x_min = min(max((int)fxm, 1), 18), y_min = min(max((int)fym, 1), 18);
        int x_max = min(max((int)fxM, 1), 18), y_max = min(max((int)fyM, 1), 18);
        if (x_max == x_min) x_min--;
        if (y_max == y_min) y_min--;
        int nx = x_max - x_min + 1, ny = y_max - y_min + 1;
        int py = p / 3, px = p % 3, ty = tid / 3, tx = tid % 3;
        int y = 2 * py - 1 + ty, x = 2 * px - 1 + tx;
        bool valid = (y >= 0 && y < 5 && x >= 0 && x < 5);
        int ys = 0, ye = 1, xs = 0, xe = 1;
        float wgt = 0.f;
        if (valid) {
            ys = y_min + (y * ny) / 5;
            ye = y_min + ((y + 1) * ny + 4) / 5;
            xs = x_min + (x * nx) / 5;
            xe = x_min + ((x + 1) * nx + 4) / 5;
            wgt = 1.f / ((float)(ye - ys) * (float)(xe - xs));
        }
        sA[tid] = (ye * 20 + xe) * 1024;
        sB[tid] = (ys * 20 + xe) * 1024;
        sC[tid] = (ye * 20 + xs) * 1024;
        sD[tid] = (ys * 20 + xs) * 1024;
        sW[tid] = wgt;
    }
    __syncthreads();
    size_t row = (size_t)bx * 9216;
    for (int t = 0; t < 9; t++) {
        float w = sW[t];
        int a = sA[t], b = sB[t], c0 = sC[t], d = sD[t];
        for (int c = tid; c < 1024; c += 256) {
            float v = (g_I[a + c] - g_I[b + c] - g_I[c0 + c] + g_I[d + c]) * w;
            __nv_bfloat16 hi = __float2bfloat16(v);
            g_Bhi[row + t * 1024 + c] = hi;
            g_Blo[row + t * 1024 + c] = __float2bfloat16(v - __bfloat162float(hi));
        }
    }
}

// ---------------------------------------------------------------------------
// conv1 as mma.sync bf16 split-precision GEMM + BN + ReLU epilogue.
// C[256 x 9216] = A[256 x 9216] * B[9216 x 9216]^T with 3 fused passes
// (Ahi*Bhi + Alo*Bhi + Ahi*Blo) accumulating into the same fp32 regs.
// Grid (72 n-tiles, 2 m-tiles), 256 thr, CTA tile 128x128, K-chunk 64,
// 2-stage cp.async double buffer, padded smem (72-el rows, conflict-free).
// Warp tile 64x32 (warp grid 2x4). Output g_h1 TRANSPOSED: [oc][n].
// ---------------------------------------------------------------------------
#define GSTRIDE 72                     // smem row stride in elements (144 B)
#define MAT_BYTES (128 * GSTRIDE * 2)  // 18432 B per matrix
#define STAGE_BYTES (4 * MAT_BYTES)    // Ahi, Alo, Bhi, Blo
#define GEMM_SMEM (2 * STAGE_BYTES)    // 147456 B
#define NCH 144                        // 9216 / 64

__global__ void __launch_bounds__(256, 1) k_gemm1(
    const float* __restrict__ b1, const float* __restrict__ g1,
    const float* __restrict__ be1, const float* __restrict__ m1,
    const float* __restrict__ v1) {
    extern __shared__ char smem[];
    unsigned int sb = smem_u32(smem);
    int tid = threadIdx.x, wid = tid >> 5, lane = tid & 31;
    int n0 = blockIdx.x * 128, m0 = blockIdx.y * 128;
    int warp_m = wid & 1, warp_n = wid >> 1;

    // loader mapping: 8 threads per row (16B each), 32 rows per pass, 4 passes
    int lrow = tid >> 3, lcol = tid & 7;  // lcol*8 elements = lcol*16 bytes

    float acc[4][4][4];
#pragma unroll
    for (int i = 0; i < 4; i++)
#pragma unroll
        for (int j = 0; j < 4; j++)
#pragma unroll
            for (int q = 0; q < 4; q++) acc[i][j][q] = 0.f;

    const __nv_bfloat16* gA[2] = {g_Ahi + (size_t)m0 * 9216, g_Alo + (size_t)m0 * 9216};
    const __nv_bfloat16* gB[2] = {g_Bhi + (size_t)n0 * 9216, g_Blo + (size_t)n0 * 9216};

    // ---- stage loader (cp.async) ----
    auto load_stage = [&](int s, int k0) {
        unsigned int st = sb + s * STAGE_BYTES;
#pragma unroll
        for (int i = 0; i < 4; i++) {
            int row = lrow + i * 32;
            unsigned int doff = row * (GSTRIDE * 2) + lcol * 16;
            size_t goff = (size_t)row * 9216 + k0 + lcol * 8;
            cpa16(st + 0 * MAT_BYTES + doff, gA[0] + goff);
            cpa16(st + 1 * MAT_BYTES + doff, gA[1] + goff);
            cpa16(st + 2 * MAT_BYTES + doff, gB[0] + goff);
            cpa16(st + 3 * MAT_BYTES + doff, gB[1] + goff);
        }
    };

    load_stage(0, 0);
    asm volatile("cp.async.commit_group;");

    // ldmatrix lane address components (byte offsets within a matrix)
    int a_row = warp_m * 64 + (lane & 15);
    int a_cb = (lane >> 4) << 4;  // 0 or 16 bytes
    int b_row = warp_n * 32 + (lane & 7) + ((lane >> 4) << 3);
    int b_cb = ((lane >> 3) & 1) << 4;

    for (int ch = 0; ch < NCH; ch++) {
        if (ch + 1 < NCH) {
            load_stage((ch + 1) & 1, (ch + 1) * 64);
            asm volatile("cp.async.commit_group;");
            asm volatile("cp.async.wait_group 1;");
        } else {
            asm volatile("cp.async.wait_group 0;");
        }
        __syncthreads();

        unsigned int st = sb + (ch & 1) * STAGE_BYTES;
        unsigned int Ah = st, Al = st + MAT_BYTES, Bh = st + 2 * MAT_BYTES, Bl = st + 3 * MAT_BYTES;

#pragma unroll
        for (int ks = 0; ks < 4; ks++) {
            unsigned int ahi[4][4], alo[4][4], bhi[8], blo[8];
            int acol = ks * 32 + a_cb;
            int bcol = ks * 32 + b_cb;
#pragma unroll
            for (int mf = 0; mf < 4; mf++) {
                unsigned int ao = (a_row + mf * 16) * (GSTRIDE * 2) + acol;
                ldsm4(ahi[mf], Ah + ao);
                ldsm4(alo[mf], Al + ao);
            }
            {
                unsigned int bo0 = b_row * (GSTRIDE * 2) + bcol;
                unsigned int bo1 = (b_row + 16) * (GSTRIDE * 2) + bcol;
                ldsm4(bhi + 0, Bh + bo0);
                ldsm4(bhi + 4, Bh + bo1);
                ldsm4(blo + 0, Bl + bo0);
                ldsm4(blo + 4, Bl + bo1);
            }
#pragma unroll
            for (int mf = 0; mf < 4; mf++) {
#pragma unroll
                for (int nf = 0; nf < 4; nf++) {
                    mma_bf16(acc[mf][nf], ahi[mf], bhi[2 * nf], bhi[2 * nf + 1]);
                    mma_bf16(acc[mf][nf], alo[mf], bhi[2 * nf], bhi[2 * nf + 1]);
                    mma_bf16(acc[mf][nf], ahi[mf], blo[2 * nf], blo[2 * nf + 1]);
                }
            }
        }
        __syncthreads();
    }

    // ---- epilogue: BN + ReLU, write g_h1[oc][n] (n pairs contiguous) ----
    int mb = m0 + warp_m * 64;
    int nb = n0 + warp_n * 32;
#pragma unroll
    for (int mf = 0; mf < 4; mf++) {
        int r0 = mb + mf * 16 + (lane >> 2);
        int r1 = r0 + 8;
        float s0 = __ldg(g1 + r0) * rsqrtf(__ldg(v1 + r0) + EPS);
        float h0 = __ldg(be1 + r0) - __ldg(m1 + r0) * s0 + __ldg(b1 + r0) * s0;
        float s1 = __ldg(g1 + r1) * rsqrtf(__ldg(v1 + r1) + EPS);
        float h1 = __ldg(be1 + r1) - __ldg(m1 + r1) * s1 + __ldg(b1 + r1) * s1;
#pragma unroll
        for (int nf = 0; nf < 4; nf++) {
            int n = nb + nf * 8 + (lane & 3) * 2;
            float2 v0, v1_;
            v0.x = fmaxf(acc[mf][nf][0] * s0 + h0, 0.f);
            v0.y = fmaxf(acc[mf][nf][1] * s0 + h0, 0.f);
            v1_.x = fmaxf(acc[mf][nf][2] * s1 + h1, 0.f);
            v1_.y = fmaxf(acc[mf][nf][3] * s1 + h1, 0.f);
            *(float2*)(g_h1 + (size_t)r0 * 9216 + n) = v0;
            *(float2*)(g_h1 + (size_t)r1 * 9216 + n) = v1_;
        }
    }
}

// ---------------------------------------------------------------------------
// conv2 (256->256, 3x3, s2, p1, 3x3 -> 2x2) + BN + ReLU, packed f32x2.
// Input g_h1 [ic][n = roi*9+p] (transposed). Output: out[roi][oc][2x2].
// ---------------------------------------------------------------------------
__global__ void __launch_bounds__(256, 2) k_conv2(
    const float* __restrict__ b2, const float* __restrict__ g2,
    const float* __restrict__ be2, const float* __restrict__ m2,
    const float* __restrict__ v2, float* __restrict__ out) {
    __shared__ float s_in[8 * 36];  // [icl][roi][p]
    int tid = threadIdx.x;
    int roiL = tid >> 6;
    int oc0 = (tid & 63) * 4;
    int roi0 = blockIdx.x * 4;

    u64 acc[4][2];
    for (int p = 0; p < 4; p++) {
        acc[p][0] = 0ull;
        acc[p][1] = 0ull;
    }

    int icl_ld = tid / 9, q_ld = tid % 9;  // threads 0..71 load
    const float* wbase = g_wT2 + oc0;

    for (int ic0 = 0; ic0 < 256; ic0 += 8) {
        __syncthreads();
        if (tid < 72) {
            // n-base for this block = roi0 * 9 (36 floats cover 4 rois x 9 pos)
            *(float4*)&s_in[icl_ld * 36 + q_ld * 4] =
                *(const float4*)(g_h1 + (size_t)(ic0 + icl_ld) * 9216 + roi0 * 9 + q_ld * 4);
        }
        __syncthreads();
#pragma unroll
        for (int icl = 0; icl < 8; icl++) {
            float in[9];
#pragma unroll
            for (int p = 0; p < 9; p++) in[p] = s_in[icl * 36 + roiL * 9 + p];
            const float* wp = wbase + (ic0 + icl) * 9 * 256;
#pragma unroll
            for (int t = 0; t < 9; t++) {
                ulonglong2 w = *(const ulonglong2*)(wp + t * 256);
                int ky = t / 3, kx = t % 3;
#pragma unroll
                for (int i = 0; i < 2; i++) {
                    int y = 2 * i - 1 + ky;
                    if (y < 0 || y > 2) continue;
#pragma unroll
                    for (int j = 0; j < 2; j++) {
                        int x = 2 * j - 1 + kx;
                        if (x < 0 || x > 2) continue;
                        u64 vv = pack2(in[y * 3 + x]);
                        int p = i * 2 + j;
                        fma2(acc[p][0], w.x, vv);
                        fma2(acc[p][1], w.y, vv);
                    }
                }
            }
        }
    }

    int roi = roi0 + roiL;
    float sc[4], sh[4];
    for (int q = 0; q < 4; q++) {
        int oc = oc0 + q;
        float s = __ldg(g2 + oc) * rsqrtf(__ldg(v2 + oc) + EPS);
        sc[q] = s;
        sh[q] = __ldg(be2 + oc) - __ldg(m2 + oc) * s + __ldg(b2 + oc) * s;
    }
    float a[4][4];
    for (int p = 0; p < 4; p++) {
        float2 x0 = unpack2(acc[p][0]);
        float2 x1 = unpack2(acc[p][1]);
        a[p][0] = x0.x;
        a[p][1] = x0.y;
        a[p][2] = x1.x;
        a[p][3] = x1.y;
    }
    for (int q = 0; q < 4; q++) {
        float4 o;
        o.x = fmaxf(a[0][q] * sc[q] + sh[q], 0.f);
        o.y = fmaxf(a[1][q] * sc[q] + sh[q], 0.f);
        o.z = fmaxf(a[2][q] * sc[q] + sh[q], 0.f);
        o.w = fmaxf(a[3][q] * sc[q] + sh[q], 0.f);
        *(float4*)(out + roi * 1024 + (oc0 + q) * 4) = o;
    }
}

// ---------------------------------------------------------------------------
extern "C" void kernel_launch(void* const* d_in, const int* in_sizes, int n_in,
                              void* d_out, int out_size) {
    const float* rois = (const float*)d_in[0];
    const float* features = (const float*)d_in[1];
    const float* w1 = (const float*)d_in[2];
    const float* b1 = (const float*)d_in[3];
    const float* g1 = (const float*)d_in[4];
    const float* be1 = (const float*)d_in[5];
    const float* m1 = (const float*)d_in[6];
    const float* v1 = (const float*)d_in[7];
    const float* w2 = (const float*)d_in[8];
    const float* b2 = (const float*)d_in[9];
    const float* g2 = (const float*)d_in[10];
    const float* be2 = (const float*)d_in[11];
    const float* m2 = (const float*)d_in[12];
    const float* v2 = (const float*)d_in[13];
    float* out = (float*)d_out;

    cudaFuncSetAttribute(k_gemm1, cudaFuncAttributeMaxDynamicSharedMemorySize, GEMM_SMEM);

    float* wT2p;
    cudaGetSymbolAddress((void**)&wT2p, g_wT2);
    k_transpose<<<dim3(72, 8), dim3(32, 8)>>>(w2, wT2p, 2304);
    k_integral<<<4, 256>>>(features);
    k_build_a<<<9216, 256>>>(w1);
    k_build_b<<<9216, 256>>>(rois);
    k_gemm1<<<dim3(72, 2), 256, GEMM_SMEM>>>(b1, g1, be1, m1, v1);
    k_conv2<<<256, 256>>>(b2, g2, be2, m2, v2, out);
}

// round 13
// speedup vs baseline: 5.1631x; 1.2237x over previous
#include <cuda_runtime.h>
#include <cuda_bf16.h>
#include <cstdint>
#include <cstddef>

typedef unsigned long long u64;
#define EPS 1e-5f

// ---- structural-sparsity tables: valid taps per output position p ----
// p = py*3+px; tap t = ky*3+kx valid iff y=2py-1+ky in [0,4] and x=2px-1+kx in [0,4]
__constant__ int c_VT[9][9] = {
    {4, 5, 7, 8, 0, 0, 0, 0, 0},
    {3, 4, 5, 6, 7, 8, 0, 0, 0},
    {3, 4, 6, 7, 0, 0, 0, 0, 0},
    {1, 2, 4, 5, 7, 8, 0, 0, 0},
    {0, 1, 2, 3, 4, 5, 6, 7, 8},
    {0, 1, 3, 4, 6, 7, 0, 0, 0},
    {1, 2, 4, 5, 0, 0, 0, 0, 0},
    {0, 1, 2, 3, 4, 5, 0, 0, 0},
    {0, 1, 3, 4, 0, 0, 0, 0, 0}};
__constant__ int c_NT[9] = {4, 6, 4, 6, 9, 6, 4, 6, 4};
__constant__ int c_PS[9] = {0, 4, 10, 14, 20, 29, 35, 39, 45};  // prefix sums of NT
__constant__ int c_PORD[9] = {4, 1, 3, 5, 7, 0, 2, 6, 8};       // heavy p first

// ---- scratch (static __device__; no allocation) ----
__device__ float g_I[20 * 20 * 1024];                  // integral image [y][x][c]
__device__ __nv_bfloat16 g_Ahi[256 * 9216];            // weights hi [oc][k=t*1024+ic]
__device__ __nv_bfloat16 g_Alo[256 * 9216];            // weights lo
__device__ __nv_bfloat16 g_Bhi[49ull * 1024 * 1024];   // packed im2col hi, per-p groups
__device__ __nv_bfloat16 g_Blo[49ull * 1024 * 1024];   // packed im2col lo
__device__ float g_h1[256 * 9216];                     // conv1 out [oc][p*1024+roi]
__device__ float g_wT2[2304 * 256];                    // conv2 weights [k][oc]

// ---- packed f32x2 helpers (conv2) ----
__device__ __forceinline__ void fma2(u64& a, u64 w, u64 v) {
    asm("fma.rn.f32x2 %0, %1, %2, %0;" : "+l"(a) : "l"(w), "l"(v));
}
__device__ __forceinline__ u64 pack2(float v) {
    u64 r;
    asm("mov.b64 %0, {%1, %1};" : "=l"(r) : "f"(v));
    return r;
}
__device__ __forceinline__ float2 unpack2(u64 a) {
    float2 f;
    asm("mov.b64 {%0, %1}, %2;" : "=f"(f.x), "=f"(f.y) : "l"(a));
    return f;
}

// ---- mma.sync / ldmatrix / cp.async helpers ----
__device__ __forceinline__ unsigned int smem_u32(const void* p) {
    unsigned int a;
    asm("{ .reg .u64 t; cvta.to.shared.u64 t, %1; cvt.u32.u64 %0, t; }" : "=r"(a) : "l"(p));
    return a;
}
__device__ __forceinline__ void ldsm4(unsigned int* r, unsigned int addr) {
    asm volatile("ldmatrix.sync.aligned.m8n8.x4.shared.b16 {%0,%1,%2,%3}, [%4];"
                 : "=r"(r[0]), "=r"(r[1]), "=r"(r[2]), "=r"(r[3]) : "r"(addr));
}
__device__ __forceinline__ void mma_bf16(float* c, const unsigned int* a,
                                         unsigned int b0, unsigned int b1) {
    asm volatile(
        "mma.sync.aligned.m16n8k16.row.col.f32.bf16.bf16.f32 "
        "{%0,%1,%2,%3}, {%4,%5,%6,%7}, {%8,%9}, {%0,%1,%2,%3};"
        : "+f"(c[0]), "+f"(c[1]), "+f"(c[2]), "+f"(c[3])
        : "r"(a[0]), "r"(a[1]), "r"(a[2]), "r"(a[3]), "r"(b0), "r"(b1));
}
__device__ __forceinline__ void cpa16(unsigned int dst, const void* src) {
    asm volatile("cp.async.cg.shared.global [%0], [%1], 16;" :: "r"(dst), "l"(src));
}

// ---------------------------------------------------------------------------
// conv2 weight transpose: in[256][K] -> out[K][256]
// ---------------------------------------------------------------------------
__global__ void k_transpose(const float* __restrict__ in, float* __restrict__ out, int K) {
    __shared__ float tile[32][33];
    int k0 = blockIdx.x * 32, o0 = blockIdx.y * 32;
    for (int r = threadIdx.y; r < 32; r += 8)
        tile[r][threadIdx.x] = in[(o0 + r) * K + k0 + threadIdx.x];
    __syncthreads();
    for (int r = threadIdx.y; r < 32; r += 8)
        out[(k0 + r) * 256 + o0 + threadIdx.x] = tile[threadIdx.x][r];
}

// ---------------------------------------------------------------------------
// Per-channel 2D integral image (19x19 -> 20x20 zero-bordered), [y][x][c]
// ---------------------------------------------------------------------------
__global__ void k_integral(const float* __restrict__ f) {
    int c = blockIdx.x * 256 + threadIdx.x;
    if (c >= 1024) return;
    float prev[19];
    g_I[c] = 0.f;
    for (int x = 0; x < 19; x++) {
        g_I[(x + 1) * 1024 + c] = 0.f;
        prev[x] = 0.f;
    }
    for (int y = 0; y < 19; y++) {
        g_I[((y + 1) * 20) * 1024 + c] = 0.f;
        float rs = 0.f;
        for (int x = 0; x < 19; x++) {
            rs += f[c * 361 + y * 19 + x];
            float cur = rs + prev[x];
            g_I[((y + 1) * 20 + x + 1) * 1024 + c] = cur;
            prev[x] = cur;
        }
    }
}

// ---------------------------------------------------------------------------
// A build: w1[oc][ic][t] -> Ahi/Alo[oc][k = t*1024+ic], bf16 hi/lo split
// ---------------------------------------------------------------------------
__global__ void k_build_a(const float* __restrict__ w1) {
    int idx = blockIdx.x * 256 + threadIdx.x;
    int m = idx / 9216, k = idx - m * 9216;
    int t = k >> 10, ic = k & 1023;
    float w = w1[m * 9216 + ic * 9 + t];
    __nv_bfloat16 hi = __float2bfloat16(w);
    g_Ahi[idx] = hi;
    g_Alo[idx] = __float2bfloat16(w - __bfloat162float(hi));
}

// ---------------------------------------------------------------------------
// B build (fused RoI pooling + im2col), SPARSE per-p packing + bf16x2 stores.
// Group p: rows are rois; columns = valid taps only (c_VT order), K_p=NT[p]*1024.
// Element base for (p, roi): 1024*(PS[p]*1024 + roi*NT[p]).
// ---------------------------------------------------------------------------
__global__ void __launch_bounds__(256) k_build_b(const float* __restrict__ rois) {
    __shared__ int sA[9], sB[9], sC[9], sD[9];
    __shared__ float sW[9];
    int bx = blockIdx.x;
    int r = bx / 9, p = bx - r * 9;
    int nt = c_NT[p];
    int tid = threadIdx.x;
    if (tid < nt) {
        const float S = 18.75f;
        float fxm = rois[r * 5 + 1] * S, fym = rois[r * 5 + 2] * S;
        float fxM = rois[r * 5 + 3] * S, fyM = rois[r * 5 + 4] * S;
        int x_min = min(max((int)fxm, 1), 18), y_min = min(max((int)fym, 1), 18);
        int x_max = min(max((int)fxM, 1), 18), y_max = min(max((int)fyM, 1), 18);
        if (x_max == x_min) x_min--;
        if (y_max == y_min) y_min--;
        int nx = x_max - x_min + 1, ny = y_max - y_min + 1;
        int t = c_VT[p][tid];
        int py = p / 3, px = p % 3, ky = t / 3, kx = t % 3;
        int y = 2 * py - 1 + ky, x = 2 * px - 1 + kx;  // always in [0,4] (valid tap)
        int ys = y_min + (y * ny) / 5;
        int ye = y_min + ((y + 1) * ny + 4) / 5;
        int xs = x_min + (x * nx) / 5;
        int xe = x_min + ((x + 1) * nx + 4) / 5;
        sA[tid] = (ye * 20 + xe) * 1024;
        sB[tid] = (ys * 20 + xe) * 1024;
        sC[tid] = (ye * 20 + xs) * 1024;
        sD[tid] = (ys * 20 + xs) * 1024;
        sW[tid] = 1.f / ((float)(ye - ys) * (float)(xe - xs));
    }
    __syncthreads();
    size_t base = 1024ull * ((size_t)c_PS[p] * 1024 + (size_t)r * nt);
    unsigned int* bhi = (unsigned int*)(g_Bhi + base);
    unsigned int* blo = (unsigned int*)(g_Blo + base);
    for (int j = 0; j < nt; j++) {
        float w = sW[j];
        int a = sA[j], b = sB[j], c0 = sC[j], d = sD[j];
        for (int c2 = tid; c2 < 512; c2 += 256) {
            int c = c2 * 2;
            float2 Ia = *(const float2*)(g_I + a + c);
            float2 Ib = *(const float2*)(g_I + b + c);
            float2 Ic = *(const float2*)(g_I + c0 + c);
            float2 Id = *(const float2*)(g_I + d + c);
            float v0 = (Ia.x - Ib.x - Ic.x + Id.x) * w;
            float v1 = (Ia.y - Ib.y - Ic.y + Id.y) * w;
            __nv_bfloat16 h0 = __float2bfloat16(v0);
            __nv_bfloat16 h1 = __float2bfloat16(v1);
            __nv_bfloat16 l0 = __float2bfloat16(v0 - __bfloat162float(h0));
            __nv_bfloat16 l1 = __float2bfloat16(v1 - __bfloat162float(h1));
            unsigned int hp = ((unsigned int)__bfloat16_as_ushort(h1) << 16) |
                              (unsigned int)__bfloat16_as_ushort(h0);
            unsigned int lp = ((unsigned int)__bfloat16_as_ushort(l1) << 16) |
                              (unsigned int)__bfloat16_as_ushort(l0);
            bhi[j * 512 + c2] = hp;
            blo[j * 512 + c2] = lp;
        }
    }
}

// ---------------------------------------------------------------------------
// conv1 GEMM (sparse per-p): C_p[256 x 1024] = A[:, valid k] * B_p^T.
// Grid (16 n-tiles of 64 rois, 2 m-tiles, 9 p heavy-first), 256 thr,
// 2 CTAs/SM. 3 fused bf16 passes. K-chunk 64, 2-stage cp.async buffer.
// Warp tile 64x16 (warp grid 2x4). Output g_h1[oc][p*1024+roi], BN+ReLU.
// ---------------------------------------------------------------------------
#define ST_AHI 0
#define ST_ALO 18432
#define ST_BHI 36864
#define ST_BLO 46080
#define STAGE_BYTES 55296
#define GEMM_SMEM 110592

__global__ void __launch_bounds__(256, 2) k_gemm1(
    const float* __restrict__ b1, const float* __restrict__ g1,
    const float* __restrict__ be1, const float* __restrict__ m1,
    const float* __restrict__ v1) {
    extern __shared__ char smem[];
    unsigned int sb = smem_u32(smem);
    int tid = threadIdx.x, wid = tid >> 5, lane = tid & 31;
    int p = c_PORD[blockIdx.z];
    int nt = c_NT[p];
    int n0 = blockIdx.x * 64;   // roi base
    int m0 = blockIdx.y * 128;  // oc base
    int warp_m = wid & 1, warp_n = wid >> 1;
    int Krow = nt * 1024;
    int NCHp = nt * 16;
    int lrow = tid >> 3, lcol = tid & 7;

    const __nv_bfloat16* gAhi = g_Ahi + (size_t)m0 * 9216;
    const __nv_bfloat16* gAlo = g_Alo + (size_t)m0 * 9216;
    size_t bbase = 1024ull * ((size_t)c_PS[p] * 1024 + (size_t)n0 * nt);
    const __nv_bfloat16* gBhi2 = g_Bhi + bbase;
    const __nv_bfloat16* gBlo2 = g_Blo + bbase;

    float acc[4][2][4];
#pragma unroll
    for (int i = 0; i < 4; i++)
#pragma unroll
        for (int j = 0; j < 2; j++)
#pragma unroll
            for (int q = 0; q < 4; q++) acc[i][j][q] = 0.f;

    auto load_stage = [&](int s, int ch) {
        unsigned int st = sb + s * STAGE_BYTES;
        int j = ch >> 4;
        size_t acol = (size_t)c_VT[p][j] * 1024 + (ch & 15) * 64 + lcol * 8;
        size_t bcol = (size_t)ch * 64 + lcol * 8;
        unsigned int doff = lrow * 144 + lcol * 16;
#pragma unroll
        for (int i = 0; i < 4; i++) {
            int row = lrow + i * 32;
            cpa16(st + ST_AHI + doff + i * 32 * 144, gAhi + (size_t)row * 9216 + acol);
            cpa16(st + ST_ALO + doff + i * 32 * 144, gAlo + (size_t)row * 9216 + acol);
        }
#pragma unroll
        for (int i = 0; i < 2; i++) {
            int row = lrow + i * 32;
            cpa16(st + ST_BHI + doff + i * 32 * 144, gBhi2 + (size_t)row * Krow + bcol);
            cpa16(st + ST_BLO + doff + i * 32 * 144, gBlo2 + (size_t)row * Krow + bcol);
        }
    };

    load_stage(0, 0);
    asm volatile("cp.async.commit_group;");

    int a_row = warp_m * 64 + (lane & 15);
    int a_cb = (lane >> 4) << 4;
    int b_row = warp_n * 16 + (lane & 7) + ((lane >> 4) << 3);
    int b_cb = ((lane >> 3) & 1) << 4;

    for (int ch = 0; ch < NCHp; ch++) {
        if (ch + 1 < NCHp) {
            load_stage((ch + 1) & 1, ch + 1);
            asm volatile("cp.async.commit_group;");
            asm volatile("cp.async.wait_group 1;");
        } else {
            asm volatile("cp.async.wait_group 0;");
        }
        __syncthreads();

        unsigned int st = sb + (ch & 1) * STAGE_BYTES;
#pragma unroll
        for (int ks = 0; ks < 4; ks++) {
            unsigned int ahi[4][4], alo[4][4], bhi[4], blo[4];
            int acol = ks * 32 + a_cb;
            int bcol = ks * 32 + b_cb;
#pragma unroll
            for (int mf = 0; mf < 4; mf++) {
                unsigned int ao = (a_row + mf * 16) * 144 + acol;
                ldsm4(ahi[mf], st + ST_AHI + ao);
                ldsm4(alo[mf], st + ST_ALO + ao);
            }
            {
                unsigned int bo = b_row * 144 + bcol;
                ldsm4(bhi, st + ST_BHI + bo);
                ldsm4(blo, st + ST_BLO + bo);
            }
#pragma unroll
            for (int mf = 0; mf < 4; mf++) {
#pragma unroll
                for (int nf = 0; nf < 2; nf++) {
                    mma_bf16(acc[mf][nf], ahi[mf], bhi[2 * nf], bhi[2 * nf + 1]);
                    mma_bf16(acc[mf][nf], alo[mf], bhi[2 * nf], bhi[2 * nf + 1]);
                    mma_bf16(acc[mf][nf], ahi[mf], blo[2 * nf], blo[2 * nf + 1]);
                }
            }
        }
        __syncthreads();
    }

    // ---- epilogue: BN + ReLU, write g_h1[oc][p*1024 + roi] ----
    int colbase = p * 1024 + n0;
#pragma unroll
    for (int mf = 0; mf < 4; mf++) {
        int r0 = m0 + warp_m * 64 + mf * 16 + (lane >> 2);
        int r1 = r0 + 8;
        float s0 = __ldg(g1 + r0) * rsqrtf(__ldg(v1 + r0) + EPS);
        float h0 = __ldg(be1 + r0) - __ldg(m1 + r0) * s0 + __ldg(b1 + r0) * s0;
        float s1 = __ldg(g1 + r1) * rsqrtf(__ldg(v1 + r1) + EPS);
        float h1 = __ldg(be1 + r1) - __ldg(m1 + r1) * s1 + __ldg(b1 + r1) * s1;
#pragma unroll
        for (int nf = 0; nf < 2; nf++) {
            int n = warp_n * 16 + nf * 8 + (lane & 3) * 2;
            float2 v0, v1_;
            v0.x = fmaxf(acc[mf][nf][0] * s0 + h0, 0.f);
            v0.y = fmaxf(acc[mf][nf][1] * s0 + h0, 0.f);
            v1_.x = fmaxf(acc[mf][nf][2] * s1 + h1, 0.f);
            v1_.y = fmaxf(acc[mf][nf][3] * s1 + h1, 0.f);
            *(float2*)(g_h1 + (size_t)r0 * 9216 + colbase + n) = v0;
            *(float2*)(g_h1 + (size_t)r1 * 9216 + colbase + n) = v1_;
        }
    }
}

// ---------------------------------------------------------------------------
// conv2 (256->256, 3x3, s2, p1, 3x3 -> 2x2) + BN + ReLU, packed f32x2.
// Input g_h1 [ic][p*1024 + roi]. Output: out[roi][oc][2x2].
// ---------------------------------------------------------------------------
__global__ void __launch_bounds__(256, 2) k_conv2(
    const float* __restrict__ b2, const float* __restrict__ g2,
    const float* __restrict__ be2, const float* __restrict__ m2,
    const float* __restrict__ v2, float* __restrict__ out) {
    __shared__ float s_in[8 * 9 * 4];  // [icl][p][roi_local]
    int tid = threadIdx.x;
    int roiL = tid >> 6;
    int oc0 = (tid & 63) * 4;
    int roi0 = blockIdx.x * 4;

    u64 acc[4][2];
    for (int p = 0; p < 4; p++) {
        acc[p][0] = 0ull;
        acc[p][1] = 0ull;
    }

    int icl_ld = tid / 9, p_ld = tid % 9;  // threads 0..71 load
    const float* wbase = g_wT2 + oc0;

    for (int ic0 = 0; ic0 < 256; ic0 += 8) {
        __syncthreads();
        if (tid < 72) {
            *(float4*)&s_in[icl_ld * 36 + p_ld * 4] =
                *(const float4*)(g_h1 + (size_t)(ic0 + icl_ld) * 9216 + p_ld * 1024 + roi0);
        }
        __syncthreads();
#pragma unroll
        for (int icl = 0; icl < 8; icl++) {
            float in[9];
#pragma unroll
            for (int p = 0; p < 9; p++) in[p] = s_in[icl * 36 + p * 4 + roiL];
            const float* wp = wbase + (ic0 + icl) * 9 * 256;
#pragma unroll
            for (int t = 0; t < 9; t++) {
                ulonglong2 w = *(const ulonglong2*)(wp + t * 256);
                int ky = t / 3, kx = t % 3;
#pragma unroll
                for (int i = 0; i < 2; i++) {
                    int y = 2 * i - 1 + ky;
                    if (y < 0 || y > 2) continue;
#pragma unroll
                    for (int j = 0; j < 2; j++) {
                        int x = 2 * j - 1 + kx;
                        if (x < 0 || x > 2) continue;
                        u64 vv = pack2(in[y * 3 + x]);
                        int p = i * 2 + j;
                        fma2(acc[p][0], w.x, vv);
                        fma2(acc[p][1], w.y, vv);
                    }
                }
            }
        }
    }

    int roi = roi0 + roiL;
    float sc[4], sh[4];
    for (int q = 0; q < 4; q++) {
        int oc = oc0 + q;
        float s = __ldg(g2 + oc) * rsqrtf(__ldg(v2 + oc) + EPS);
        sc[q] = s;
        sh[q] = __ldg(be2 + oc) - __ldg(m2 + oc) * s + __ldg(b2 + oc) * s;
    }
    float a[4][4];
    for (int p = 0; p < 4; p++) {
        float2 x0 = unpack2(acc[p][0]);
        float2 x1 = unpack2(acc[p][1]);
        a[p][0] = x0.x;
        a[p][1] = x0.y;
        a[p][2] = x1.x;
        a[p][3] = x1.y;
    }
    for (int q = 0; q < 4; q++) {
        float4 o;
        o.x = fmaxf(a[0][q] * sc[q] + sh[q], 0.f);
        o.y = fmaxf(a[1][q] * sc[q] + sh[q], 0.f);
        o.z = fmaxf(a[2][q] * sc[q] + sh[q], 0.f);
        o.w = fmaxf(a[3][q] * sc[q] + sh[q], 0.f);
        *(float4*)(out + roi * 1024 + (oc0 + q) * 4) = o;
    }
}

// ---------------------------------------------------------------------------
extern "C" void kernel_launch(void* const* d_in, const int* in_sizes, int n_in,
                              void* d_out, int out_size) {
    const float* rois = (const float*)d_in[0];
    const float* features = (const float*)d_in[1];
    const float* w1 = (const float*)d_in[2];
    const float* b1 = (const float*)d_in[3];
    const float* g1 = (const float*)d_in[4];
    const float* be1 = (const float*)d_in[5];
    const float* m1 = (const float*)d_in[6];
    const float* v1 = (const float*)d_in[7];
    const float* w2 = (const float*)d_in[8];
    const float* b2 = (const float*)d_in[9];
    const float* g2 = (const float*)d_in[10];
    const float* be2 = (const float*)d_in[11];
    const float* m2 = (const float*)d_in[12];
    const float* v2 = (const float*)d_in[13];
    float* out = (float*)d_out;

    cudaFuncSetAttribute(k_gemm1, cudaFuncAttributeMaxDynamicSharedMemorySize, GEMM_SMEM);

    float* wT2p;
    cudaGetSymbolAddress((void**)&wT2p, g_wT2);
    k_transpose<<<dim3(72, 8), dim3(32, 8)>>>(w2, wT2p, 2304);
    k_integral<<<4, 256>>>(features);
    k_build_a<<<9216, 256>>>(w1);
    k_build_b<<<9216, 256>>>(rois);
    k_gemm1<<<dim3(16, 2, 9), 256, GEMM_SMEM>>>(b1, g1, be1, m1, v1);
    k_conv2<<<256, 256>>>(b2, g2, be2, m2, v2, out);
}

// round 15
// speedup vs baseline: 5.9856x; 1.1593x over previous
#include <cuda_runtime.h>
#include <cuda_bf16.h>
#include <cstdint>
#include <cstddef>

typedef unsigned long long u64;
#define EPS 1e-5f

// ---- conv1 structural-sparsity tables (5x5 in, 3x3 out, stride2 pad1) ----
__constant__ int c_VT[9][9] = {
    {4, 5, 7, 8, 0, 0, 0, 0, 0},
    {3, 4, 5, 6, 7, 8, 0, 0, 0},
    {3, 4, 6, 7, 0, 0, 0, 0, 0},
    {1, 2, 4, 5, 7, 8, 0, 0, 0},
    {0, 1, 2, 3, 4, 5, 6, 7, 8},
    {0, 1, 3, 4, 6, 7, 0, 0, 0},
    {1, 2, 4, 5, 0, 0, 0, 0, 0},
    {0, 1, 2, 3, 4, 5, 0, 0, 0},
    {0, 1, 3, 4, 0, 0, 0, 0, 0}};
__constant__ int c_NT[9] = {4, 6, 4, 6, 9, 6, 4, 6, 4};
__constant__ int c_PS[9] = {0, 4, 10, 14, 20, 29, 35, 39, 45};
__constant__ int c_PORD[9] = {4, 1, 3, 5, 7, 0, 2, 6, 8};

// ---- conv2 tables (3x3 in, 2x2 out, stride2 pad1): 4 valid taps per pos ----
// c_VT2[p2][j] = tap t in w2; c_PIN2[p2][j] = source plane p in h1 (y*3+x)
__constant__ int c_VT2[4][4] = {{4, 5, 7, 8}, {3, 4, 6, 7}, {1, 2, 4, 5}, {0, 1, 3, 4}};
__constant__ int c_PIN2[4][4] = {{0, 1, 3, 4}, {1, 2, 4, 5}, {3, 4, 6, 7}, {4, 5, 7, 8}};

// ---- scratch (static __device__; no allocation) ----
__device__ float g_I[20 * 20 * 1024];                 // integral image [y][x][c]
__device__ __nv_bfloat16 g_Ahi[256 * 9216];           // conv1 weights hi [oc][t*1024+ic]
__device__ __nv_bfloat16 g_Alo[256 * 9216];
__device__ __nv_bfloat16 g_Bhi[49ull * 1024 * 1024];  // packed im2col hi (per-p groups)
__device__ __nv_bfloat16 g_Blo[49ull * 1024 * 1024];
__device__ float g_h1[256 * 9216];                    // conv1 out [oc][p*1024+roi]
__device__ __nv_bfloat16 g_A2hi[256 * 2304];          // conv2 weights hi [oc][t*256+ic]
__device__ __nv_bfloat16 g_A2lo[256 * 2304];
__device__ __nv_bfloat16 g_h1Thi[9216ull * 256];      // h1 transposed hi [col][ic]
__device__ __nv_bfloat16 g_h1Tlo[9216ull * 256];

// ---- mma.sync / ldmatrix / cp.async helpers ----
__device__ __forceinline__ unsigned int smem_u32(const void* p) {
    unsigned int a;
    asm("{ .reg .u64 t; cvta.to.shared.u64 t, %1; cvt.u32.u64 %0, t; }" : "=r"(a) : "l"(p));
    return a;
}
__device__ __forceinline__ void ldsm4(unsigned int* r, unsigned int addr) {
    asm volatile("ldmatrix.sync.aligned.m8n8.x4.shared.b16 {%0,%1,%2,%3}, [%4];"
                 : "=r"(r[0]), "=r"(r[1]), "=r"(r[2]), "=r"(r[3]) : "r"(addr));
}
__device__ __forceinline__ void mma_bf16(float* c, const unsigned int* a,
                                         unsigned int b0, unsigned int b1) {
    asm volatile(
        "mma.sync.aligned.m16n8k16.row.col.f32.bf16.bf16.f32 "
        "{%0,%1,%2,%3}, {%4,%5,%6,%7}, {%8,%9}, {%0,%1,%2,%3};"
        : "+f"(c[0]), "+f"(c[1]), "+f"(c[2]), "+f"(c[3])
        : "r"(a[0]), "r"(a[1]), "r"(a[2]), "r"(a[3]), "r"(b0), "r"(b1));
}
__device__ __forceinline__ void cpa16(unsigned int dst, const void* src) {
    asm volatile("cp.async.cg.shared.global [%0], [%1], 16;" :: "r"(dst), "l"(src));
}

// ---------------------------------------------------------------------------
// Per-channel 2D integral image (19x19 -> 20x20 zero-bordered), [y][x][c]
// ---------------------------------------------------------------------------
__global__ void k_integral(const float* __restrict__ f) {
    int c = blockIdx.x * 256 + threadIdx.x;
    if (c >= 1024) return;
    float prev[19];
    g_I[c] = 0.f;
    for (int x = 0; x < 19; x++) {
        g_I[(x + 1) * 1024 + c] = 0.f;
        prev[x] = 0.f;
    }
    for (int y = 0; y < 19; y++) {
        g_I[((y + 1) * 20) * 1024 + c] = 0.f;
        float rs = 0.f;
        for (int x = 0; x < 19; x++) {
            rs += f[c * 361 + y * 19 + x];
            float cur = rs + prev[x];
            g_I[((y + 1) * 20 + x + 1) * 1024 + c] = cur;
            prev[x] = cur;
        }
    }
}

// ---------------------------------------------------------------------------
// A builds: fp32 -> bf16 hi/lo splits
// ---------------------------------------------------------------------------
__global__ void k_build_a(const float* __restrict__ w1) {
    int idx = blockIdx.x * 256 + threadIdx.x;
    int m = idx / 9216, k = idx - m * 9216;
    int t = k >> 10, ic = k & 1023;
    float w = w1[m * 9216 + ic * 9 + t];
    __nv_bfloat16 hi = __float2bfloat16(w);
    g_Ahi[idx] = hi;
    g_Alo[idx] = __float2bfloat16(w - __bfloat162float(hi));
}

__global__ void k_build_a2(const float* __restrict__ w2) {
    int idx = blockIdx.x * 256 + threadIdx.x;
    int m = idx / 2304, k = idx - m * 2304;
    int t = k >> 8, ic = k & 255;
    float w = w2[m * 2304 + ic * 9 + t];
    __nv_bfloat16 hi = __float2bfloat16(w);
    g_A2hi[idx] = hi;
    g_A2lo[idx] = __float2bfloat16(w - __bfloat162float(hi));
}

// ---------------------------------------------------------------------------
// B build (fused RoI pooling + im2col), sparse per-p packing, bf16x2 stores.
// ---------------------------------------------------------------------------
__global__ void __launch_bounds__(256) k_build_b(const float* __restrict__ rois) {
    __shared__ int sA[9], sB[9], sC[9], sD[9];
    __shared__ float sW[9];
    int bx = blockIdx.x;
    int r = bx / 9, p = bx - r * 9;
    int nt = c_NT[p];
    int tid = threadIdx.x;
    if (tid < nt) {
        const float S = 18.75f;
        float fxm = rois[r * 5 + 1] * S, fym = rois[r * 5 + 2] * S;
        float fxM = rois[r * 5 + 3] * S, fyM = rois[r * 5 + 4] * S;
        int x_min = min(max((int)fxm, 1), 18), y_min = min(max((int)fym, 1), 18);
        int x_max = min(max((int)fxM, 1), 18), y_max = min(max((int)fyM, 1), 18);
        if (x_max == x_min) x_min--;
        if (y_max == y_min) y_min--;
        int nx = x_max - x_min + 1, ny = y_max - y_min + 1;
        int t = c_VT[p][tid];
        int py = p / 3, px = p % 3, ky = t / 3, kx = t % 3;
        int y = 2 * py - 1 + ky, x = 2 * px - 1 + kx;
        int ys = y_min + (y * ny) / 5;
        int ye = y_min + ((y + 1) * ny + 4) / 5;
        int xs = x_min + (x * nx) / 5;
        int xe = x_min + ((x + 1) * nx + 4) / 5;
        sA[tid] = (ye * 20 + xe) * 1024;
        sB[tid] = (ys * 20 + xe) * 1024;
        sC[tid] = (ye * 20 + xs) * 1024;
        sD[tid] = (ys * 20 + xs) * 1024;
        sW[tid] = 1.f / ((float)(ye - ys) * (float)(xe - xs));
    }
    __syncthreads();
    size_t base = 1024ull * ((size_t)c_PS[p] * 1024 + (size_t)r * nt);
    unsigned int* bhi = (unsigned int*)(g_Bhi + base);
    unsigned int* blo = (unsigned int*)(g_Blo + base);
    for (int j = 0; j < nt; j++) {
        float w = sW[j];
        int a = sA[j], b = sB[j], c0 = sC[j], d = sD[j];
        for (int c2 = tid; c2 < 512; c2 += 256) {
            int c = c2 * 2;
            float2 Ia = *(const float2*)(g_I + a + c);
            float2 Ib = *(const float2*)(g_I + b + c);
            float2 Ic = *(const float2*)(g_I + c0 + c);
            float2 Id = *(const float2*)(g_I + d + c);
            float v0 = (Ia.x - Ib.x - Ic.x + Id.x) * w;
            float v1 = (Ia.y - Ib.y - Ic.y + Id.y) * w;
            __nv_bfloat16 h0 = __float2bfloat16(v0);
            __nv_bfloat16 h1 = __float2bfloat16(v1);
            __nv_bfloat16 l0 = __float2bfloat16(v0 - __bfloat162float(h0));
            __nv_bfloat16 l1 = __float2bfloat16(v1 - __bfloat162float(h1));
            unsigned int hp = ((unsigned int)__bfloat16_as_ushort(h1) << 16) |
                              (unsigned int)__bfloat16_as_ushort(h0);
            unsigned int lp = ((unsigned int)__bfloat16_as_ushort(l1) << 16) |
                              (unsigned int)__bfloat16_as_ushort(l0);
            bhi[j * 512 + c2] = hp;
            blo[j * 512 + c2] = lp;
        }
    }
}

// ---------------------------------------------------------------------------
// h1 repack: g_h1 [oc][col] fp32 -> g_h1Thi/lo [col][ic] bf16 (32x32 tiles)
// ---------------------------------------------------------------------------
__global__ void k_h1t() {
    __shared__ float tile[32][33];
    int c0 = blockIdx.x * 32, o0 = blockIdx.y * 32;
    int tx = threadIdx.x, ty = threadIdx.y;
    for (int r = ty; r < 32; r += 8)
        tile[r][tx] = g_h1[(size_t)(o0 + r) * 9216 + c0 + tx];
    __syncthreads();
    for (int r = ty; r < 32; r += 8) {
        float v = tile[tx][r];  // = h1[o0+tx][c0+r]
        __nv_bfloat16 hi = __float2bfloat16(v);
        size_t o = (size_t)(c0 + r) * 256 + o0 + tx;
        g_h1Thi[o] = hi;
        g_h1Tlo[o] = __float2bfloat16(v - __bfloat162float(hi));
    }
}

// ---------------------------------------------------------------------------
// conv1 GEMM (sparse per-p), 3-pass bf16, identical to R13 (proven).
// ---------------------------------------------------------------------------
#define ST_AHI 0
#define ST_ALO 18432
#define ST_BHI 36864
#define ST_BLO 46080
#define STAGE_BYTES 55296
#define GEMM_SMEM 110592

__global__ void __launch_bounds__(256, 2) k_gemm1(
    const float* __restrict__ b1, const float* __restrict__ g1,
    const float* __restrict__ be1, const float* __restrict__ m1,
    const float* __restrict__ v1) {
    extern __shared__ char smem[];
    unsigned int sb = smem_u32(smem);
    int tid = threadIdx.x, wid = tid >> 5, lane = tid & 31;
    int p = c_PORD[blockIdx.z];
    int nt = c_NT[p];
    int n0 = blockIdx.x * 64;
    int m0 = blockIdx.y * 128;
    int warp_m = wid & 1, warp_n = wid >> 1;
    int Krow = nt * 1024;
    int NCHp = nt * 16;
    int lrow = tid >> 3, lcol = tid & 7;

    const __nv_bfloat16* gAhi = g_Ahi + (size_t)m0 * 9216;
    const __nv_bfloat16* gAlo = g_Alo + (size_t)m0 * 9216;
    size_t bbase = 1024ull * ((size_t)c_PS[p] * 1024 + (size_t)n0 * nt);
    const __nv_bfloat16* gBhi2 = g_Bhi + bbase;
    const __nv_bfloat16* gBlo2 = g_Blo + bbase;

    float acc[4][2][4];
#pragma unroll
    for (int i = 0; i < 4; i++)
#pragma unroll
        for (int j = 0; j < 2; j++)
#pragma unroll
            for (int q = 0; q < 4; q++) acc[i][j][q] = 0.f;

    auto load_stage = [&](int s, int ch) {
        unsigned int st = sb + s * STAGE_BYTES;
        int j = ch >> 4;
        size_t acol = (size_t)c_VT[p][j] * 1024 + (ch & 15) * 64 + lcol * 8;
        size_t bcol = (size_t)ch * 64 + lcol * 8;
        unsigned int doff = lrow * 144 + lcol * 16;
#pragma unroll
        for (int i = 0; i < 4; i++) {
            int row = lrow + i * 32;
            cpa16(st + ST_AHI + doff + i * 32 * 144, gAhi + (size_t)row * 9216 + acol);
            cpa16(st + ST_ALO + doff + i * 32 * 144, gAlo + (size_t)row * 9216 + acol);
        }
#pragma unroll
        for (int i = 0; i < 2; i++) {
            int row = lrow + i * 32;
            cpa16(st + ST_BHI + doff + i * 32 * 144, gBhi2 + (size_t)row * Krow + bcol);
            cpa16(st + ST_BLO + doff + i * 32 * 144, gBlo2 + (size_t)row * Krow + bcol);
        }
    };

    load_stage(0, 0);
    asm volatile("cp.async.commit_group;");

    int a_row = warp_m * 64 + (lane & 15);
    int a_cb = (lane >> 4) << 4;
    int b_row = warp_n * 16 + (lane & 7) + ((lane >> 4) << 3);
    int b_cb = ((lane >> 3) & 1) << 4;

    for (int ch = 0; ch < NCHp; ch++) {
        if (ch + 1 < NCHp) {
            load_stage((ch + 1) & 1, ch + 1);
            asm volatile("cp.async.commit_group;");
            asm volatile("cp.async.wait_group 1;");
        } else {
            asm volatile("cp.async.wait_group 0;");
        }
        __syncthreads();

        unsigned int st = sb + (ch & 1) * STAGE_BYTES;
#pragma unroll
        for (int ks = 0; ks < 4; ks++) {
            unsigned int ahi[4][4], alo[4][4], bhi[4], blo[4];
            int acol = ks * 32 + a_cb;
            int bcol = ks * 32 + b_cb;
#pragma unroll
            for (int mf = 0; mf < 4; mf++) {
                unsigned int ao = (a_row + mf * 16) * 144 + acol;
                ldsm4(ahi[mf], st + ST_AHI + ao);
                ldsm4(alo[mf], st + ST_ALO + ao);
            }
            {
                unsigned int bo = b_row * 144 + bcol;
                ldsm4(bhi, st + ST_BHI + bo);
                ldsm4(blo, st + ST_BLO + bo);
            }
#pragma unroll
            for (int mf = 0; mf < 4; mf++) {
#pragma unroll
                for (int nf = 0; nf < 2; nf++) {
                    mma_bf16(acc[mf][nf], ahi[mf], bhi[2 * nf], bhi[2 * nf + 1]);
                    mma_bf16(acc[mf][nf], alo[mf], bhi[2 * nf], bhi[2 * nf + 1]);
                    mma_bf16(acc[mf][nf], ahi[mf], blo[2 * nf], blo[2 * nf + 1]);
                }
            }
        }
        __syncthreads();
    }

    int colbase = p * 1024 + n0;
#pragma unroll
    for (int mf = 0; mf < 4; mf++) {
        int r0 = m0 + warp_m * 64 + mf * 16 + (lane >> 2);
        int r1 = r0 + 8;
        float s0 = __ldg(g1 + r0) * rsqrtf(__ldg(v1 + r0) + EPS);
        float h0 = __ldg(be1 + r0) - __ldg(m1 + r0) * s0 + __ldg(b1 + r0) * s0;
        float s1 = __ldg(g1 + r1) * rsqrtf(__ldg(v1 + r1) + EPS);
        float h1 = __ldg(be1 + r1) - __ldg(m1 + r1) * s1 + __ldg(b1 + r1) * s1;
#pragma unroll
        for (int nf = 0; nf < 2; nf++) {
            int n = warp_n * 16 + nf * 8 + (lane & 3) * 2;
            float2 v0, v1_;
            v0.x = fmaxf(acc[mf][nf][0] * s0 + h0, 0.f);
            v0.y = fmaxf(acc[mf][nf][1] * s0 + h0, 0.f);
            v1_.x = fmaxf(acc[mf][nf][2] * s1 + h1, 0.f);
            v1_.y = fmaxf(acc[mf][nf][3] * s1 + h1, 0.f);
            *(float2*)(g_h1 + (size_t)r0 * 9216 + colbase + n) = v0;
            *(float2*)(g_h1 + (size_t)r1 * 9216 + colbase + n) = v1_;
        }
    }
}

// ---------------------------------------------------------------------------
// conv2 GEMM (sparse per-p2): C[256 x 1024] = A2[:, valid k2] * B2^T, where
// B2 rows are gathered on the fly from g_h1T (no materialization).
// Grid (16 n-tiles of 64 rois, 2 m-tiles, 4 p2). K_p2 = 4 taps * 256 = 1024.
// 3-pass bf16. Epilogue: BN + ReLU -> out[roi][oc][p2].
// ---------------------------------------------------------------------------
__global__ void __launch_bounds__(256, 2) k_gemm2(
    const float* __restrict__ b2, const float* __restrict__ g2,
    const float* __restrict__ be2, const float* __restrict__ m2,
    const float* __restrict__ v2, float* __restrict__ out) {
    extern __shared__ char smem[];
    unsigned int sb = smem_u32(smem);
    int tid = threadIdx.x, wid = tid >> 5, lane = tid & 31;
    int p2 = blockIdx.z;
    int n0 = blockIdx.x * 64;
    int m0 = blockIdx.y * 128;
    int warp_m = wid & 1, warp_n = wid >> 1;
    int lrow = tid >> 3, lcol = tid & 7;

    const __nv_bfloat16* gAhi = g_A2hi + (size_t)m0 * 2304;
    const __nv_bfloat16* gAlo = g_A2lo + (size_t)m0 * 2304;

    float acc[4][2][4];
#pragma unroll
    for (int i = 0; i < 4; i++)
#pragma unroll
        for (int j = 0; j < 2; j++)
#pragma unroll
            for (int q = 0; q < 4; q++) acc[i][j][q] = 0.f;

    auto load_stage = [&](int s, int ch) {
        unsigned int st = sb + s * STAGE_BYTES;
        int j = ch >> 2;             // tap index 0..3
        int ic0 = (ch & 3) * 64;     // ic chunk base
        size_t acol = (size_t)c_VT2[p2][j] * 256 + ic0 + lcol * 8;
        int pin = c_PIN2[p2][j];
        unsigned int doff = lrow * 144 + lcol * 16;
#pragma unroll
        for (int i = 0; i < 4; i++) {
            int row = lrow + i * 32;
            cpa16(st + ST_AHI + doff + i * 32 * 144, gAhi + (size_t)row * 2304 + acol);
            cpa16(st + ST_ALO + doff + i * 32 * 144, gAlo + (size_t)row * 2304 + acol);
        }
#pragma unroll
        for (int i = 0; i < 2; i++) {
            int row = lrow + i * 32;
            size_t src = (size_t)(pin * 1024 + n0 + row) * 256 + ic0 + lcol * 8;
            cpa16(st + ST_BHI + doff + i * 32 * 144, g_h1Thi + src);
            cpa16(st + ST_BLO + doff + i * 32 * 144, g_h1Tlo + src);
        }
    };

    load_stage(0, 0);
    asm volatile("cp.async.commit_group;");

    int a_row = warp_m * 64 + (lane & 15);
    int a_cb = (lane >> 4) << 4;
    int b_row = warp_n * 16 + (lane & 7) + ((lane >> 4) << 3);
    int b_cb = ((lane >> 3) & 1) << 4;

    for (int ch = 0; ch < 16; ch++) {
        if (ch + 1 < 16) {
            load_stage((ch + 1) & 1, ch + 1);
            asm volatile("cp.async.commit_group;");
            asm volatile("cp.async.wait_group 1;");
        } else {
            asm volatile("cp.async.wait_group 0;");
        }
        __syncthreads();

        unsigned int st = sb + (ch & 1) * STAGE_BYTES;
#pragma unroll
        for (int ks = 0; ks < 4; ks++) {
            unsigned int ahi[4][4], alo[4][4], bhi[4], blo[4];
            int acol = ks * 32 + a_cb;
            int bcol = ks * 32 + b_cb;
#pragma unroll
            for (int mf = 0; mf < 4; mf++) {
                unsigned int ao = (a_row + mf * 16) * 144 + acol;
                ldsm4(ahi[mf], st + ST_AHI + ao);
                ldsm4(alo[mf], st + ST_ALO + ao);
            }
            {
                unsigned int bo = b_row * 144 + bcol;
                ldsm4(bhi, st + ST_BHI + bo);
                ldsm4(blo, st + ST_BLO + bo);
            }
#pragma unroll
            for (int mf = 0; mf < 4; mf++) {
#pragma unroll
                for (int nf = 0; nf < 2; nf++) {
                    mma_bf16(acc[mf][nf], ahi[mf], bhi[2 * nf], bhi[2 * nf + 1]);
                    mma_bf16(acc[mf][nf], alo[mf], bhi[2 * nf], bhi[2 * nf + 1]);
                    mma_bf16(acc[mf][nf], ahi[mf], blo[2 * nf], blo[2 * nf + 1]);
                }
            }
        }
        __syncthreads();
    }

    // epilogue: out[roi*1024 + oc*4 + p2]
#pragma unroll
    for (int mf = 0; mf < 4; mf++) {
        int r0 = m0 + warp_m * 64 + mf * 16 + (lane >> 2);
        int r1 = r0 + 8;
        float s0 = __ldg(g2 + r0) * rsqrtf(__ldg(v2 + r0) + EPS);
        float h0 = __ldg(be2 + r0) - __ldg(m2 + r0) * s0 + __ldg(b2 + r0) * s0;
        float s1 = __ldg(g2 + r1) * rsqrtf(__ldg(v2 + r1) + EPS);
        float h1 = __ldg(be2 + r1) - __ldg(m2 + r1) * s1 + __ldg(b2 + r1) * s1;
#pragma unroll
        for (int nf = 0; nf < 2; nf++) {
            int n = warp_n * 16 + nf * 8 + (lane & 3) * 2;
            int roiA = n0 + n, roiB = roiA + 1;
            out[roiA * 1024 + r0 * 4 + p2] = fmaxf(acc[mf][nf][0] * s0 + h0, 0.f);
            out[roiB * 1024 + r0 * 4 + p2] = fmaxf(acc[mf][nf][1] * s0 + h0, 0.f);
            out[roiA * 1024 + r1 * 4 + p2] = fmaxf(acc[mf][nf][2] * s1 + h1, 0.f);
            out[roiB * 1024 + r1 * 4 + p2] = fmaxf(acc[mf][nf][3] * s1 + h1, 0.f);
        }
    }
}

// ---------------------------------------------------------------------------
extern "C" void kernel_launch(void* const* d_in, const int* in_sizes, int n_in,
                              void* d_out, int out_size) {
    const float* rois = (const float*)d_in[0];
    const float* features = (const float*)d_in[1];
    const float* w1 = (const float*)d_in[2];
    const float* b1 = (const float*)d_in[3];
    const float* g1 = (const float*)d_in[4];
    const float* be1 = (const float*)d_in[5];
    const float* m1 = (const float*)d_in[6];
    const float* v1 = (const float*)d_in[7];
    const float* w2 = (const float*)d_in[8];
    const float* b2 = (const float*)d_in[9];
    const float* g2 = (const float*)d_in[10];
    const float* be2 = (const float*)d_in[11];
    const float* m2 = (const float*)d_in[12];
    const float* v2 = (const float*)d_in[13];
    float* out = (float*)d_out;

    cudaFuncSetAttribute(k_gemm1, cudaFuncAttributeMaxDynamicSharedMemorySize, GEMM_SMEM);
    cudaFuncSetAttribute(k_gemm2, cudaFuncAttributeMaxDynamicSharedMemorySize, GEMM_SMEM);

    // Launch order chosen so k_gemm1 is the 4th launch (the one ncu captures).
    k_integral<<<4, 256>>>(features);
    k_build_a<<<9216, 256>>>(w1);
    k_build_b<<<9216, 256>>>(rois);
    k_gemm1<<<dim3(16, 2, 9), 256, GEMM_SMEM>>>(b1, g1, be1, m1, v1);
    k_build_a2<<<2304, 256>>>(w2);
    k_h1t<<<dim3(288, 8), dim3(32, 8)>>>();
    k_gemm2<<<dim3(16, 2, 4), 256, GEMM_SMEM>>>(b2, g2, be2, m2, v2, out);
}

// round 17
// speedup vs baseline: 7.3528x; 1.2284x over previous
#include <cuda_runtime.h>
#include <cuda_bf16.h>
#include <cuda_fp16.h>
#include <cstdint>
#include <cstddef>

typedef unsigned long long u64;
#define EPS 1e-5f

// ---- conv1 structural-sparsity tables (5x5 in, 3x3 out, stride2 pad1) ----
__constant__ int c_VT[9][9] = {
    {4, 5, 7, 8, 0, 0, 0, 0, 0},
    {3, 4, 5, 6, 7, 8, 0, 0, 0},
    {3, 4, 6, 7, 0, 0, 0, 0, 0},
    {1, 2, 4, 5, 7, 8, 0, 0, 0},
    {0, 1, 2, 3, 4, 5, 6, 7, 8},
    {0, 1, 3, 4, 6, 7, 0, 0, 0},
    {1, 2, 4, 5, 0, 0, 0, 0, 0},
    {0, 1, 2, 3, 4, 5, 0, 0, 0},
    {0, 1, 3, 4, 0, 0, 0, 0, 0}};
__constant__ int c_NT[9] = {4, 6, 4, 6, 9, 6, 4, 6, 4};
__constant__ int c_PS[9] = {0, 4, 10, 14, 20, 29, 35, 39, 45};
__constant__ int c_PORD[9] = {4, 1, 3, 5, 7, 0, 2, 6, 8};

// ---- conv2 tables (3x3 in, 2x2 out, stride2 pad1): 4 valid taps per pos ----
__constant__ int c_VT2[4][4] = {{4, 5, 7, 8}, {3, 4, 6, 7}, {1, 2, 4, 5}, {0, 1, 3, 4}};
__constant__ int c_PIN2[4][4] = {{0, 1, 3, 4}, {1, 2, 4, 5}, {3, 4, 6, 7}, {4, 5, 7, 8}};

// ---- scratch (static __device__; no allocation) ----
__device__ float g_I[20 * 20 * 1024];             // integral image [y][x][c]
__device__ __half g_Ahi[256 * 9216];              // conv1 weights hi fp16 [oc][t*1024+ic]
__device__ __half g_Alo[256 * 9216];              // conv1 weights lo fp16
__device__ __half g_B16[49ull * 1024 * 1024];     // packed im2col fp16 (per-p groups)
__device__ float g_h1[256 * 9216];                // conv1 out [oc][p*1024+roi]
__device__ __nv_bfloat16 g_A2hi[256 * 2304];      // conv2 weights hi bf16 [oc][t*256+ic]
__device__ __nv_bfloat16 g_A2lo[256 * 2304];
__device__ __nv_bfloat16 g_h1Thi[9216ull * 256];  // h1 transposed hi [col][ic]
__device__ __nv_bfloat16 g_h1Tlo[9216ull * 256];

// ---- mma.sync / ldmatrix / cp.async helpers ----
__device__ __forceinline__ unsigned int smem_u32(const void* p) {
    unsigned int a;
    asm("{ .reg .u64 t; cvta.to.shared.u64 t, %1; cvt.u32.u64 %0, t; }" : "=r"(a) : "l"(p));
    return a;
}
__device__ __forceinline__ void ldsm4(unsigned int* r, unsigned int addr) {
    asm volatile("ldmatrix.sync.aligned.m8n8.x4.shared.b16 {%0,%1,%2,%3}, [%4];"
                 : "=r"(r[0]), "=r"(r[1]), "=r"(r[2]), "=r"(r[3]) : "r"(addr));
}
__device__ __forceinline__ void mma_bf16(float* c, const unsigned int* a,
                                         unsigned int b0, unsigned int b1) {
    asm volatile(
        "mma.sync.aligned.m16n8k16.row.col.f32.bf16.bf16.f32 "
        "{%0,%1,%2,%3}, {%4,%5,%6,%7}, {%8,%9}, {%0,%1,%2,%3};"
        : "+f"(c[0]), "+f"(c[1]), "+f"(c[2]), "+f"(c[3])
        : "r"(a[0]), "r"(a[1]), "r"(a[2]), "r"(a[3]), "r"(b0), "r"(b1));
}
__device__ __forceinline__ void mma_f16(float* c, const unsigned int* a,
                                        unsigned int b0, unsigned int b1) {
    asm volatile(
        "mma.sync.aligned.m16n8k16.row.col.f32.f16.f16.f32 "
        "{%0,%1,%2,%3}, {%4,%5,%6,%7}, {%8,%9}, {%0,%1,%2,%3};"
        : "+f"(c[0]), "+f"(c[1]), "+f"(c[2]), "+f"(c[3])
        : "r"(a[0]), "r"(a[1]), "r"(a[2]), "r"(a[3]), "r"(b0), "r"(b1));
}
__device__ __forceinline__ void cpa16(unsigned int dst, const void* src) {
    asm volatile("cp.async.cg.shared.global [%0], [%1], 16;" :: "r"(dst), "l"(src));
}

// ---------------------------------------------------------------------------
// Per-channel 2D integral image (19x19 -> 20x20 zero-bordered), [y][x][c]
// ---------------------------------------------------------------------------
__global__ void k_integral(const float* __restrict__ f) {
    int c = blockIdx.x * 256 + threadIdx.x;
    if (c >= 1024) return;
    float prev[19];
    g_I[c] = 0.f;
    for (int x = 0; x < 19; x++) {
        g_I[(x + 1) * 1024 + c] = 0.f;
        prev[x] = 0.f;
    }
    for (int y = 0; y < 19; y++) {
        g_I[((y + 1) * 20) * 1024 + c] = 0.f;
        float rs = 0.f;
        for (int x = 0; x < 19; x++) {
            rs += f[c * 361 + y * 19 + x];
            float cur = rs + prev[x];
            g_I[((y + 1) * 20 + x + 1) * 1024 + c] = cur;
            prev[x] = cur;
        }
    }
}

// ---------------------------------------------------------------------------
// A builds
// ---------------------------------------------------------------------------
__global__ void k_build_a(const float* __restrict__ w1) {
    int idx = blockIdx.x * 256 + threadIdx.x;
    int m = idx / 9216, k = idx - m * 9216;
    int t = k >> 10, ic = k & 1023;
    float w = w1[m * 9216 + ic * 9 + t];
    __half hi = __float2half_rn(w);
    g_Ahi[idx] = hi;
    g_Alo[idx] = __float2half_rn(w - __half2float(hi));
}

__global__ void k_build_a2(const float* __restrict__ w2) {
    int idx = blockIdx.x * 256 + threadIdx.x;
    int m = idx / 2304, k = idx - m * 2304;
    int t = k >> 8, ic = k & 255;
    float w = w2[m * 2304 + ic * 9 + t];
    __nv_bfloat16 hi = __float2bfloat16(w);
    g_A2hi[idx] = hi;
    g_A2lo[idx] = __float2bfloat16(w - __bfloat162float(hi));
}

// ---------------------------------------------------------------------------
// B build (fused RoI pooling + im2col), sparse per-p packing, fp16x2 stores.
// ---------------------------------------------------------------------------
__global__ void __launch_bounds__(256) k_build_b(const float* __restrict__ rois) {
    __shared__ int sA[9], sB[9], sC[9], sD[9];
    __shared__ float sW[9];
    int bx = blockIdx.x;
    int r = bx / 9, p = bx - r * 9;
    int nt = c_NT[p];
    int tid = threadIdx.x;
    if (tid < nt) {
        const float S = 18.75f;
        float fxm = rois[r * 5 + 1] * S, fym = rois[r * 5 + 2] * S;
        float fxM = rois[r * 5 + 3] * S, fyM = rois[r * 5 + 4] * S;
        int x_min = min(max((int)fxm, 1), 18), y_min = min(max((int)fym, 1), 18);
        int x_max = min(max((int)fxM, 1), 18), y_max = min(max((int)fyM, 1), 18);
        if (x_max == x_min) x_min--;
        if (y_max == y_min) y_min--;
        int nx = x_max - x_min + 1, ny = y_max - y_min + 1;
        int t = c_VT[p][tid];
        int py = p / 3, px = p % 3, ky = t / 3, kx = t % 3;
        int y = 2 * py - 1 + ky, x = 2 * px - 1 + kx;
        int ys = y_min + (y * ny) / 5;
        int ye = y_min + ((y + 1) * ny + 4) / 5;
        int xs = x_min + (x * nx) / 5;
        int xe = x_min + ((x + 1) * nx + 4) / 5;
        sA[tid] = (ye * 20 + xe) * 1024;
        sB[tid] = (ys * 20 + xe) * 1024;
        sC[tid] = (ye * 20 + xs) * 1024;
        sD[tid] = (ys * 20 + xs) * 1024;
        sW[tid] = 1.f / ((float)(ye - ys) * (float)(xe - xs));
    }
    __syncthreads();
    size_t base = 1024ull * ((size_t)c_PS[p] * 1024 + (size_t)r * nt);
    unsigned int* bp = (unsigned int*)(g_B16 + base);
    for (int j = 0; j < nt; j++) {
        float w = sW[j];
        int a = sA[j], b = sB[j], c0 = sC[j], d = sD[j];
        for (int c2 = tid; c2 < 512; c2 += 256) {
            int c = c2 * 2;
            float2 Ia = *(const float2*)(g_I + a + c);
            float2 Ib = *(const float2*)(g_I + b + c);
            float2 Ic = *(const float2*)(g_I + c0 + c);
            float2 Id = *(const float2*)(g_I + d + c);
            float v0 = (Ia.x - Ib.x - Ic.x + Id.x) * w;
            float v1 = (Ia.y - Ib.y - Ic.y + Id.y) * w;
            __half h0 = __float2half_rn(v0);
            __half h1 = __float2half_rn(v1);
            unsigned int hp = ((unsigned int)__half_as_ushort(h1) << 16) |
                              (unsigned int)__half_as_ushort(h0);
            bp[j * 512 + c2] = hp;
        }
    }
}

// ---------------------------------------------------------------------------
// h1 repack: g_h1 [oc][col] fp32 -> g_h1Thi/lo [col][ic] bf16 (32x32 tiles)
// ---------------------------------------------------------------------------
__global__ void k_h1t() {
    __shared__ float tile[32][33];
    int c0 = blockIdx.x * 32, o0 = blockIdx.y * 32;
    int tx = threadIdx.x, ty = threadIdx.y;
    for (int r = ty; r < 32; r += 8)
        tile[r][tx] = g_h1[(size_t)(o0 + r) * 9216 + c0 + tx];
    __syncthreads();
    for (int r = ty; r < 32; r += 8) {
        float v = tile[tx][r];
        __nv_bfloat16 hi = __float2bfloat16(v);
        size_t o = (size_t)(c0 + r) * 256 + o0 + tx;
        g_h1Thi[o] = hi;
        g_h1Tlo[o] = __float2bfloat16(v - __bfloat162float(hi));
    }
}

// ---------------------------------------------------------------------------
// conv1 GEMM (sparse per-p), 2-pass fp16 (A split hi/lo, B single).
// Grid (16 n-tiles of 64, 2 m-tiles, 9 p heavy-first), 256 thr, 2 CTAs/SM.
// Single-barrier pipeline: wait -> barrier -> issue next load -> compute.
// ---------------------------------------------------------------------------
#define ST_AHI 0
#define ST_ALO 18432
#define ST_B 36864
#define STAGE_BYTES 46080
#define GEMM1_SMEM 92160

__global__ void __launch_bounds__(256, 2) k_gemm1(
    const float* __restrict__ b1, const float* __restrict__ g1,
    const float* __restrict__ be1, const float* __restrict__ m1,
    const float* __restrict__ v1) {
    extern __shared__ char smem[];
    unsigned int sb = smem_u32(smem);
    int tid = threadIdx.x, wid = tid >> 5, lane = tid & 31;
    int p = c_PORD[blockIdx.z];
    int nt = c_NT[p];
    int n0 = blockIdx.x * 64;
    int m0 = blockIdx.y * 128;
    int warp_m = wid & 1, warp_n = wid >> 1;
    int Krow = nt * 1024;
    int NCHp = nt * 16;
    int lrow = tid >> 3, lcol = tid & 7;

    const __half* gAhi = g_Ahi + (size_t)m0 * 9216;
    const __half* gAlo = g_Alo + (size_t)m0 * 9216;
    size_t bbase = 1024ull * ((size_t)c_PS[p] * 1024 + (size_t)n0 * nt);
    const __half* gB = g_B16 + bbase;

    float acc[4][2][4];
#pragma unroll
    for (int i = 0; i < 4; i++)
#pragma unroll
        for (int j = 0; j < 2; j++)
#pragma unroll
            for (int q = 0; q < 4; q++) acc[i][j][q] = 0.f;

    auto load_stage = [&](int s, int ch) {
        unsigned int st = sb + s * STAGE_BYTES;
        int j = ch >> 4;
        size_t acol = (size_t)c_VT[p][j] * 1024 + (ch & 15) * 64 + lcol * 8;
        size_t bcol = (size_t)ch * 64 + lcol * 8;
        unsigned int doff = lrow * 144 + lcol * 16;
#pragma unroll
        for (int i = 0; i < 4; i++) {
            int row = lrow + i * 32;
            cpa16(st + ST_AHI + doff + i * 32 * 144, gAhi + (size_t)row * 9216 + acol);
            cpa16(st + ST_ALO + doff + i * 32 * 144, gAlo + (size_t)row * 9216 + acol);
        }
#pragma unroll
        for (int i = 0; i < 2; i++) {
            int row = lrow + i * 32;
            cpa16(st + ST_B + doff + i * 32 * 144, gB + (size_t)row * Krow + bcol);
        }
    };

    load_stage(0, 0);
    asm volatile("cp.async.commit_group;");

    int a_row = warp_m * 64 + (lane & 15);
    int a_cb = (lane >> 4) << 4;
    int b_row = warp_n * 16 + (lane & 7) + ((lane >> 4) << 3);
    int b_cb = ((lane >> 3) & 1) << 4;

    for (int ch = 0; ch < NCHp; ch++) {
        asm volatile("cp.async.wait_group 0;");
        __syncthreads();
        if (ch + 1 < NCHp) {
            load_stage((ch + 1) & 1, ch + 1);
            asm volatile("cp.async.commit_group;");
        }

        unsigned int st = sb + (ch & 1) * STAGE_BYTES;
#pragma unroll
        for (int ks = 0; ks < 4; ks++) {
            unsigned int ahi[4][4], alo[4][4], bf[4];
            int acol = ks * 32 + a_cb;
            int bcol = ks * 32 + b_cb;
#pragma unroll
            for (int mf = 0; mf < 4; mf++) {
                unsigned int ao = (a_row + mf * 16) * 144 + acol;
                ldsm4(ahi[mf], st + ST_AHI + ao);
                ldsm4(alo[mf], st + ST_ALO + ao);
            }
            ldsm4(bf, st + ST_B + b_row * 144 + bcol);
#pragma unroll
            for (int mf = 0; mf < 4; mf++) {
#pragma unroll
                for (int nf = 0; nf < 2; nf++) {
                    mma_f16(acc[mf][nf], ahi[mf], bf[2 * nf], bf[2 * nf + 1]);
                    mma_f16(acc[mf][nf], alo[mf], bf[2 * nf], bf[2 * nf + 1]);
                }
            }
        }
    }

    int colbase = p * 1024 + n0;
#pragma unroll
    for (int mf = 0; mf < 4; mf++) {
        int r0 = m0 + warp_m * 64 + mf * 16 + (lane >> 2);
        int r1 = r0 + 8;
        float s0 = __ldg(g1 + r0) * rsqrtf(__ldg(v1 + r0) + EPS);
        float h0 = __ldg(be1 + r0) - __ldg(m1 + r0) * s0 + __ldg(b1 + r0) * s0;
        float s1 = __ldg(g1 + r1) * rsqrtf(__ldg(v1 + r1) + EPS);
        float h1 = __ldg(be1 + r1) - __ldg(m1 + r1) * s1 + __ldg(b1 + r1) * s1;
#pragma unroll
        for (int nf = 0; nf < 2; nf++) {
            int n = warp_n * 16 + nf * 8 + (lane & 3) * 2;
            float2 v0, v1_;
            v0.x = fmaxf(acc[mf][nf][0] * s0 + h0, 0.f);
            v0.y = fmaxf(acc[mf][nf][1] * s0 + h0, 0.f);
            v1_.x = fmaxf(acc[mf][nf][2] * s1 + h1, 0.f);
            v1_.y = fmaxf(acc[mf][nf][3] * s1 + h1, 0.f);
            *(float2*)(g_h1 + (size_t)r0 * 9216 + colbase + n) = v0;
            *(float2*)(g_h1 + (size_t)r1 * 9216 + colbase + n) = v1_;
        }
    }
}

// ---------------------------------------------------------------------------
// conv2 GEMM (sparse per-p2), 3-pass bf16, B gathered from g_h1T.
// Single-barrier pipeline. Epilogue: BN + ReLU -> out[roi][oc][p2].
// ---------------------------------------------------------------------------
#define ST2_AHI 0
#define ST2_ALO 18432
#define ST2_BHI 36864
#define ST2_BLO 46080
#define STAGE2_BYTES 55296
#define GEMM2_SMEM 110592

__global__ void __launch_bounds__(256, 2) k_gemm2(
    const float* __restrict__ b2, const float* __restrict__ g2,
    const float* __restrict__ be2, const float* __restrict__ m2,
    const float* __restrict__ v2, float* __restrict__ out) {
    extern __shared__ char smem[];
    unsigned int sb = smem_u32(smem);
    int tid = threadIdx.x, wid = tid >> 5, lane = tid & 31;
    int p2 = blockIdx.z;
    int n0 = blockIdx.x * 64;
    int m0 = blockIdx.y * 128;
    int warp_m = wid & 1, warp_n = wid >> 1;
    int lrow = tid >> 3, lcol = tid & 7;

    const __nv_bfloat16* gAhi = g_A2hi + (size_t)m0 * 2304;
    const __nv_bfloat16* gAlo = g_A2lo + (size_t)m0 * 2304;

    float acc[4][2][4];
#pragma unroll
    for (int i = 0; i < 4; i++)
#pragma unroll
        for (int j = 0; j < 2; j++)
#pragma unroll
            for (int q = 0; q < 4; q++) acc[i][j][q] = 0.f;

    auto load_stage = [&](int s, int ch) {
        unsigned int st = sb + s * STAGE2_BYTES;
        int j = ch >> 2;
        int ic0 = (ch & 3) * 64;
        size_t acol = (size_t)c_VT2[p2][j] * 256 + ic0 + lcol * 8;
        int pin = c_PIN2[p2][j];
        unsigned int doff = lrow * 144 + lcol * 16;
#pragma unroll
        for (int i = 0; i < 4; i++) {
            int row = lrow + i * 32;
            cpa16(st + ST2_AHI + doff + i * 32 * 144, gAhi + (size_t)row * 2304 + acol);
            cpa16(st + ST2_ALO + doff + i * 32 * 144, gAlo + (size_t)row * 2304 + acol);
        }
#pragma unroll
        for (int i = 0; i < 2; i++) {
            int row = lrow + i * 32;
            size_t src = (size_t)(pin * 1024 + n0 + row) * 256 + ic0 + lcol * 8;
            cpa16(st + ST2_BHI + doff + i * 32 * 144, g_h1Thi + src);
            cpa16(st + ST2_BLO + doff + i * 32 * 144, g_h1Tlo + src);
        }
    };

    load_stage(0, 0);
    asm volatile("cp.async.commit_group;");

    int a_row = warp_m * 64 + (lane & 15);
    int a_cb = (lane >> 4) << 4;
    int b_row = warp_n * 16 + (lane & 7) + ((lane >> 4) << 3);
    int b_cb = ((lane >> 3) & 1) << 4;

    for (int ch = 0; ch < 16; ch++) {
        asm volatile("cp.async.wait_group 0;");
        __syncthreads();
        if (ch + 1 < 16) {
            load_stage((ch + 1) & 1, ch + 1);
            asm volatile("cp.async.commit_group;");
        }

        unsigned int st = sb + (ch & 1) * STAGE2_BYTES;
#pragma unroll
        for (int ks = 0; ks < 4; ks++) {
            unsigned int ahi[4][4], alo[4][4], bhi[4], blo[4];
            int acol = ks * 32 + a_cb;
            int bcol = ks * 32 + b_cb;
#pragma unroll
            for (int mf = 0; mf < 4; mf++) {
                unsigned int ao = (a_row + mf * 16) * 144 + acol;
                ldsm4(ahi[mf], st + ST2_AHI + ao);
                ldsm4(alo[mf], st + ST2_ALO + ao);
            }
            {
                unsigned int bo = b_row * 144 + bcol;
                ldsm4(bhi, st + ST2_BHI + bo);
                ldsm4(blo, st + ST2_BLO + bo);
            }
#pragma unroll
            for (int mf = 0; mf < 4; mf++) {
#pragma unroll
                for (int nf = 0; nf < 2; nf++) {
                    mma_bf16(acc[mf][nf], ahi[mf], bhi[2 * nf], bhi[2 * nf + 1]);
                    mma_bf16(acc[mf][nf], alo[mf], bhi[2 * nf], bhi[2 * nf + 1]);
                    mma_bf16(acc[mf][nf], ahi[mf], blo[2 * nf], blo[2 * nf + 1]);
                }
            }
        }
    }

#pragma unroll
    for (int mf = 0; mf < 4; mf++) {
        int r0 = m0 + warp_m * 64 + mf * 16 + (lane >> 2);
        int r1 = r0 + 8;
        float s0 = __ldg(g2 + r0) * rsqrtf(__ldg(v2 + r0) + EPS);
        float h0 = __ldg(be2 + r0) - __ldg(m2 + r0) * s0 + __ldg(b2 + r0) * s0;
        float s1 = __ldg(g2 + r1) * rsqrtf(__ldg(v2 + r1) + EPS);
        float h1 = __ldg(be2 + r1) - __ldg(m2 + r1) * s1 + __ldg(b2 + r1) * s1;
#pragma unroll
        for (int nf = 0; nf < 2; nf++) {
            int n = warp_n * 16 + nf * 8 + (lane & 3) * 2;
            int roiA = n0 + n, roiB = roiA + 1;
            out[roiA * 1024 + r0 * 4 + p2] = fmaxf(acc[mf][nf][0] * s0 + h0, 0.f);
            out[roiB * 1024 + r0 * 4 + p2] = fmaxf(acc[mf][nf][1] * s0 + h0, 0.f);
            out[roiA * 1024 + r1 * 4 + p2] = fmaxf(acc[mf][nf][2] * s1 + h1, 0.f);
            out[roiB * 1024 + r1 * 4 + p2] = fmaxf(acc[mf][nf][3] * s1 + h1, 0.f);
        }
    }
}

// ---------------------------------------------------------------------------
extern "C" void kernel_launch(void* const* d_in, const int* in_sizes, int n_in,
                              void* d_out, int out_size) {
    const float* rois = (const float*)d_in[0];
    const float* features = (const float*)d_in[1];
    const float* w1 = (const float*)d_in[2];
    const float* b1 = (const float*)d_in[3];
    const float* g1 = (const float*)d_in[4];
    const float* be1 = (const float*)d_in[5];
    const float* m1 = (const float*)d_in[6];
    const float* v1 = (const float*)d_in[7];
    const float* w2 = (const float*)d_in[8];
    const float* b2 = (const float*)d_in[9];
    const float* g2 = (const float*)d_in[10];
    const float* be2 = (const float*)d_in[11];
    const float* m2 = (const float*)d_in[12];
    const float* v2 = (const float*)d_in[13];
    float* out = (float*)d_out;

    cudaFuncSetAttribute(k_gemm1, cudaFuncAttributeMaxDynamicSharedMemorySize, GEMM1_SMEM);
    cudaFuncSetAttribute(k_gemm2, cudaFuncAttributeMaxDynamicSharedMemorySize, GEMM2_SMEM);

    // Launch order keeps k_gemm1 as the 4th launch (the one ncu captures).
    k_integral<<<4, 256>>>(features);
    k_build_a<<<9216, 256>>>(w1);
    k_build_b<<<9216, 256>>>(rois);
    k_gemm1<<<dim3(16, 2, 9), 256, GEMM1_SMEM>>>(b1, g1, be1, m1, v1);
    k_build_a2<<<2304, 256>>>(w2);
    k_h1t<<<dim3(288, 8), dim3(32, 8)>>>();
    k_gemm2<<<dim3(16, 2, 4), 256, GEMM2_SMEM>>>(b2, g2, be2, m2, v2, out);
}